// round 4
// baseline (speedup 1.0000x reference)
#include <cuda_runtime.h>
#include <math.h>
#include <stdint.h>

// ---------------- problem constants ----------------
#define Bz   32
#define Sz   4
#define QLz  12
#define Dz   10
#define DLz  40
#define Vz   32000
#define Ez   256
#define Hqz  256
#define Hdz  256
#define Hsz  512

#define NQ     128
#define NDOC   1280
#define QLANES 256
#define DLANES 2560
#define NDEC   96
#define TDEC   11
#define NEGF   (-1000000000.0f)

// GEMM modes
#define MODE_STORE 0   // C = acc + bias
#define MODE_ACC   1   // C += acc
#define MODE_CELL  2   // fused LSTM cell epilogue (acc + xgates -> h,c,rmax)

// ---------------- scratch ----------------
__device__ float g_qGates[QLz * QLANES * 4 * Hqz];          // interleaved
__device__ float g_dGates[DLz * DLANES * 4 * Hdz];          // interleaved
__device__ float g_decGates[TDEC * NDEC * 4 * Hsz];         // interleaved
__device__ float g_logits[NDEC * Vz];

__device__ float g_qh0[QLANES * Hqz], g_qh1[QLANES * Hqz];
__device__ float g_qc[QLANES * Hqz], g_qrmax[QLANES * Hqz];
__device__ float g_dh0[DLANES * Hdz], g_dh1[DLANES * Hdz];
__device__ float g_dc[DLANES * Hdz], g_drmax[DLANES * Hdz];
__device__ float g_encq[NQ * 2 * Hqz];
__device__ float g_encd[NDOC * 2 * Hdz];
__device__ float g_sessH[Bz * Hsz], g_sessC[Bz * Hsz];
__device__ float g_histH[Sz * Bz * Hsz], g_histC[Sz * Bz * Hsz];
__device__ float g_comb[Bz * Hsz];
__device__ float g_sgates[Bz * 4 * Hsz];
__device__ float g_decH0[NDEC * Hsz], g_decH1[NDEC * Hsz], g_decC[NDEC * Hsz];

__device__ int g_qTok[QLz * QLANES];
__device__ int g_dTok[DLz * DLANES];
__device__ int g_decTok[TDEC * NDEC];
__device__ int g_decTgt[TDEC * NDEC];

__device__ int g_permD[NDOC];
__device__ int g_ilaneD[NDOC];
__device__ int g_slenD[NDOC];
__device__ int g_cntF[DLz];
__device__ int g_cntB[DLz];

__device__ float g_click, g_dloss, g_dcnt;

__device__ __forceinline__ float sigf(float x) { return 1.0f / (1.0f + expf(-x)); }

// weight row mapping for interleaved gate layout: out col c -> orig row
__device__ __forceinline__ int wmap(int c, int Hn, int interleave) {
    return interleave ? ((c & 3) * Hn + (c >> 2)) : c;
}

// =======================================================================
// BIG GEMM: 128x128 tile, 8x8/thread, modes: store/acc/cell
// =======================================================================
__global__ __launch_bounds__(256) void gemm_big(
    const float* __restrict__ A, int lda,
    const int* __restrict__ tok, const float* __restrict__ emb,
    const float* __restrict__ W0, const float* __restrict__ W1, int ldw,
    const float* __restrict__ b0, const float* __restrict__ b1,
    float* __restrict__ C, int ldc,
    int M, int N, int K,
    int lanes, int halfLanes, int mode, int interleave,
    const int* __restrict__ cntF, const int* __restrict__ cntB,
    float* __restrict__ hOut, float* __restrict__ cState,
    float* __restrict__ rmax, const int* __restrict__ lens, int T, int t)
{
    const int row0 = blockIdx.y * 128;
    const int col0 = blockIdx.x * 128;
    const int Hn = N >> 2;

    const int lane0 = row0 % lanes;
    if (cntF) {
        const int tt = row0 / lanes;
        if (lane0 < halfLanes) { if (lane0 >= cntF[tt]) return; }
        else                   { if (lane0 - halfLanes >= cntB[tt]) return; }
    }
    const int dir = (lane0 < halfLanes) ? 0 : 1;
    const float* W    = dir ? W1 : W0;
    const float* bias = dir ? b1 : b0;

    __shared__ float As[16][128];
    __shared__ float Ws[16][128];

    const int tid = threadIdx.x;
    const int tx = tid & 15;
    const int ty = tid >> 4;
    const int lr = tid >> 1;
    const int lk = (tid & 1) << 3;

    const int ar = row0 + lr;
    const bool aok = (ar < M);
    const float* arow;
    if (tok) arow = emb + (size_t)tok[aok ? ar : 0] * K;
    else     arow = A + (size_t)(aok ? ar : 0) * lda;
    const float* wrow = W + (size_t)wmap(col0 + lr, Hn, interleave) * ldw;

    float acc[8][8];
#pragma unroll
    for (int i = 0; i < 8; i++)
#pragma unroll
        for (int j = 0; j < 8; j++) acc[i][j] = 0.0f;

    float4 av0, av1, wv0, wv1;
    {
        av0 = aok ? *(const float4*)(arow + lk)     : make_float4(0,0,0,0);
        av1 = aok ? *(const float4*)(arow + lk + 4) : make_float4(0,0,0,0);
        wv0 = *(const float4*)(wrow + lk);
        wv1 = *(const float4*)(wrow + lk + 4);
        As[lk+0][lr]=av0.x; As[lk+1][lr]=av0.y; As[lk+2][lr]=av0.z; As[lk+3][lr]=av0.w;
        As[lk+4][lr]=av1.x; As[lk+5][lr]=av1.y; As[lk+6][lr]=av1.z; As[lk+7][lr]=av1.w;
        Ws[lk+0][lr]=wv0.x; Ws[lk+1][lr]=wv0.y; Ws[lk+2][lr]=wv0.z; Ws[lk+3][lr]=wv0.w;
        Ws[lk+4][lr]=wv1.x; Ws[lk+5][lr]=wv1.y; Ws[lk+6][lr]=wv1.z; Ws[lk+7][lr]=wv1.w;
    }
    __syncthreads();

    for (int k0 = 0; k0 < K; k0 += 16) {
        const bool more = (k0 + 16) < K;
        if (more) {
            const int kn = k0 + 16 + lk;
            av0 = aok ? *(const float4*)(arow + kn)     : make_float4(0,0,0,0);
            av1 = aok ? *(const float4*)(arow + kn + 4) : make_float4(0,0,0,0);
            wv0 = *(const float4*)(wrow + kn);
            wv1 = *(const float4*)(wrow + kn + 4);
        }
#pragma unroll
        for (int k = 0; k < 16; k++) {
            float a[8], w[8];
            float4 t0 = *(const float4*)&As[k][ty*4];
            float4 t1 = *(const float4*)&As[k][64 + ty*4];
            float4 u0 = *(const float4*)&Ws[k][tx*4];
            float4 u1 = *(const float4*)&Ws[k][64 + tx*4];
            a[0]=t0.x; a[1]=t0.y; a[2]=t0.z; a[3]=t0.w;
            a[4]=t1.x; a[5]=t1.y; a[6]=t1.z; a[7]=t1.w;
            w[0]=u0.x; w[1]=u0.y; w[2]=u0.z; w[3]=u0.w;
            w[4]=u1.x; w[5]=u1.y; w[6]=u1.z; w[7]=u1.w;
#pragma unroll
            for (int i = 0; i < 8; i++)
#pragma unroll
                for (int j = 0; j < 8; j++)
                    acc[i][j] += a[i] * w[j];
        }
        __syncthreads();
        if (more) {
            As[lk+0][lr]=av0.x; As[lk+1][lr]=av0.y; As[lk+2][lr]=av0.z; As[lk+3][lr]=av0.w;
            As[lk+4][lr]=av1.x; As[lk+5][lr]=av1.y; As[lk+6][lr]=av1.z; As[lk+7][lr]=av1.w;
            Ws[lk+0][lr]=wv0.x; Ws[lk+1][lr]=wv0.y; Ws[lk+2][lr]=wv0.z; Ws[lk+3][lr]=wv0.w;
            Ws[lk+4][lr]=wv1.x; Ws[lk+5][lr]=wv1.y; Ws[lk+6][lr]=wv1.z; Ws[lk+7][lr]=wv1.w;
            __syncthreads();
        }
    }

    if (mode == MODE_CELL) {
#pragma unroll
        for (int ih = 0; ih < 2; ih++) {
#pragma unroll
            for (int i = 0; i < 4; i++) {
                const int r = row0 + ih*64 + ty*4 + i;
                if (r >= M) continue;
                bool valid = true;
                if (lens) {
                    int n = (r < halfLanes) ? r : r - halfLanes;
                    int len = lens[n];
                    valid = (r < halfLanes) ? (t < len) : (t >= T - len);
                }
                if (!valid) continue;
#pragma unroll
                for (int jh = 0; jh < 2; jh++) {
                    const int cc = col0 + jh*64 + tx*4;
                    const int j = cc >> 2;
                    float4 xg = *(const float4*)(C + (size_t)r * ldc + cc);
                    float gi = acc[ih*4+i][jh*4+0] + xg.x;
                    float gf = acc[ih*4+i][jh*4+1] + xg.y;
                    float gg = acc[ih*4+i][jh*4+2] + xg.z;
                    float go = acc[ih*4+i][jh*4+3] + xg.w;
                    float cp = cState[(size_t)r * Hn + j];
                    float cn = sigf(gf) * cp + sigf(gi) * tanhf(gg);
                    float hn = sigf(go) * tanhf(cn);
                    cState[(size_t)r * Hn + j] = cn;
                    hOut[(size_t)r * Hn + j] = hn;
                    if (rmax) {
                        float rm = rmax[(size_t)r * Hn + j];
                        rmax[(size_t)r * Hn + j] = (hn > rm) ? hn : rm;
                    }
                }
            }
        }
        return;
    }

#pragma unroll
    for (int ih = 0; ih < 2; ih++) {
#pragma unroll
        for (int i = 0; i < 4; i++) {
            const int r = row0 + ih*64 + ty*4 + i;
            if (r >= M) continue;
            float* cp = C + (size_t)r * ldc + col0;
#pragma unroll
            for (int jh = 0; jh < 2; jh++) {
                const int c = jh*64 + tx*4;
                float4 v;
                v.x = acc[ih*4+i][jh*4+0];
                v.y = acc[ih*4+i][jh*4+1];
                v.z = acc[ih*4+i][jh*4+2];
                v.w = acc[ih*4+i][jh*4+3];
                if (mode == MODE_ACC) {
                    float4 o = *(const float4*)(cp + c);
                    v.x += o.x; v.y += o.y; v.z += o.z; v.w += o.w;
                } else if (bias) {
                    const int cc = col0 + c;
                    if (interleave) {
                        const int j = cc >> 2;
                        v.x += bias[j]; v.y += bias[Hn + j];
                        v.z += bias[2*Hn + j]; v.w += bias[3*Hn + j];
                    } else {
                        float4 o = *(const float4*)(bias + cc);
                        v.x += o.x; v.y += o.y; v.z += o.z; v.w += o.w;
                    }
                }
                *(float4*)(cp + c) = v;
            }
        }
    }
}

// =======================================================================
// SMALL GEMM: 64x64 tile, 4x4/thread, modes: store/acc/cell
// =======================================================================
__global__ __launch_bounds__(256) void gemm_small(
    const float* __restrict__ A, int lda,
    const int* __restrict__ tok, const float* __restrict__ emb,
    const float* __restrict__ W0, const float* __restrict__ W1, int ldw,
    const float* __restrict__ b0, const float* __restrict__ b1,
    float* __restrict__ C, int ldc,
    int M, int N, int K,
    int lanes, int halfLanes, int mode, int interleave,
    float* __restrict__ hOut, float* __restrict__ cState,
    float* __restrict__ rmax, const int* __restrict__ lens, int T, int t)
{
    __shared__ float As[16][65];
    __shared__ float Ws[16][65];

    const int tid  = threadIdx.x;
    const int row0 = blockIdx.y * 64;
    const int col0 = blockIdx.x * 64;
    const int Hn = N >> 2;

    const int dir = ((row0 % lanes) < halfLanes) ? 0 : 1;
    const float* W    = dir ? W1 : W0;
    const float* bias = dir ? b1 : b0;

    const int lr = tid >> 2;
    const int lk = (tid & 3) << 2;
    const int ty4 = (tid >> 4) << 2;
    const int tx4 = (tid & 15) << 2;

    float acc[4][4];
#pragma unroll
    for (int i = 0; i < 4; i++)
#pragma unroll
        for (int j = 0; j < 4; j++) acc[i][j] = 0.0f;

    const int ar = row0 + lr;
    const float* arow;
    if (tok) arow = emb + (size_t)tok[(ar < M) ? ar : 0] * K;
    else     arow = A + (size_t)((ar < M) ? ar : 0) * lda;
    const float* wrow = W + (size_t)wmap(col0 + lr, Hn, interleave) * ldw;
    const bool arow_ok = (ar < M);

    for (int k0 = 0; k0 < K; k0 += 16) {
        float4 av = *(const float4*)(arow + k0 + lk);
        if (!arow_ok) av = make_float4(0.f, 0.f, 0.f, 0.f);
        float4 wv = *(const float4*)(wrow + k0 + lk);
        As[lk + 0][lr] = av.x; As[lk + 1][lr] = av.y;
        As[lk + 2][lr] = av.z; As[lk + 3][lr] = av.w;
        Ws[lk + 0][lr] = wv.x; Ws[lk + 1][lr] = wv.y;
        Ws[lk + 2][lr] = wv.z; Ws[lk + 3][lr] = wv.w;
        __syncthreads();
#pragma unroll
        for (int k = 0; k < 16; k++) {
            float a0 = As[k][ty4 + 0], a1 = As[k][ty4 + 1];
            float a2 = As[k][ty4 + 2], a3 = As[k][ty4 + 3];
            float w0 = Ws[k][tx4 + 0], w1 = Ws[k][tx4 + 1];
            float w2 = Ws[k][tx4 + 2], w3 = Ws[k][tx4 + 3];
            acc[0][0] += a0 * w0; acc[0][1] += a0 * w1; acc[0][2] += a0 * w2; acc[0][3] += a0 * w3;
            acc[1][0] += a1 * w0; acc[1][1] += a1 * w1; acc[1][2] += a1 * w2; acc[1][3] += a1 * w3;
            acc[2][0] += a2 * w0; acc[2][1] += a2 * w1; acc[2][2] += a2 * w2; acc[2][3] += a2 * w3;
            acc[3][0] += a3 * w0; acc[3][1] += a3 * w1; acc[3][2] += a3 * w2; acc[3][3] += a3 * w3;
        }
        __syncthreads();
    }

    if (mode == MODE_CELL) {
        const int cc = col0 + tx4;
        const int j = cc >> 2;
#pragma unroll
        for (int i = 0; i < 4; i++) {
            const int r = row0 + ty4 + i;
            if (r >= M) continue;
            bool valid = true;
            if (lens) {
                int n = (r < halfLanes) ? r : r - halfLanes;
                int len = lens[n];
                valid = (r < halfLanes) ? (t < len) : (t >= T - len);
            }
            if (!valid) continue;
            float4 xg = *(const float4*)(C + (size_t)r * ldc + cc);
            float gi = acc[i][0] + xg.x;
            float gf = acc[i][1] + xg.y;
            float gg = acc[i][2] + xg.z;
            float go = acc[i][3] + xg.w;
            float cp = cState[(size_t)r * Hn + j];
            float cn = sigf(gf) * cp + sigf(gi) * tanhf(gg);
            float hn = sigf(go) * tanhf(cn);
            cState[(size_t)r * Hn + j] = cn;
            hOut[(size_t)r * Hn + j] = hn;
            if (rmax) {
                float rm = rmax[(size_t)r * Hn + j];
                rmax[(size_t)r * Hn + j] = (hn > rm) ? hn : rm;
            }
        }
        return;
    }

#pragma unroll
    for (int i = 0; i < 4; i++) {
        int r = row0 + ty4 + i;
        if (r >= M) continue;
        float* cp = C + (size_t)r * ldc + col0 + tx4;
#pragma unroll
        for (int jj = 0; jj < 4; jj++) {
            float v = acc[i][jj];
            if (mode == MODE_ACC) v += cp[jj];
            else if (bias) {
                const int cc = col0 + tx4 + jj;
                v += bias[wmap(cc, Hn, interleave)];
            }
            cp[jj] = v;
        }
    }
}

// =======================================================================
// tf32 tensor-core logits GEMM: C[96][32000] = H[96][512] . W^T + bias
// block: 256 thr (8 warps), N-tile 256, warp does 96x32; grid.x = 125
// =======================================================================
__device__ __forceinline__ uint32_t f2tf(float f) {
    uint32_t u;
    asm("cvt.rna.tf32.f32 %0, %1;" : "=r"(u) : "f"(f));
    return u;
}
__device__ __forceinline__ void mma_tf32(float* d, uint32_t a0, uint32_t a1,
                                         uint32_t a2, uint32_t a3,
                                         uint32_t b0, uint32_t b1) {
    asm volatile(
        "mma.sync.aligned.m16n8k8.row.col.f32.tf32.tf32.f32 "
        "{%0,%1,%2,%3}, {%4,%5,%6,%7}, {%8,%9}, {%0,%1,%2,%3};\n"
        : "+f"(d[0]), "+f"(d[1]), "+f"(d[2]), "+f"(d[3])
        : "r"(a0), "r"(a1), "r"(a2), "r"(a3), "r"(b0), "r"(b1));
}

__global__ __launch_bounds__(256) void k_logits_tf32(
    const float* __restrict__ Hc,    // [96][512]
    const float* __restrict__ W,     // [32000][512]
    const float* __restrict__ bias,  // [32000]
    float* __restrict__ out)         // [96][32000]
{
    __shared__ float As[96][33];
    __shared__ float Ws[256][33];
    const int tid = threadIdx.x;
    const int warp = tid >> 5, lane = tid & 31;
    const int g = lane >> 2, cq = lane & 3;
    const int ncol0 = blockIdx.x * 256;
    const int wn0 = warp * 32;

    float acc[6][4][4];
#pragma unroll
    for (int m = 0; m < 6; m++)
#pragma unroll
        for (int n = 0; n < 4; n++)
#pragma unroll
            for (int v = 0; v < 4; v++) acc[m][n][v] = 0.0f;

    for (int k0 = 0; k0 < Hsz; k0 += 32) {
        for (int i = tid; i < 96 * 32; i += 256) {
            int m = i >> 5, k = i & 31;
            As[m][k] = __uint_as_float(f2tf(Hc[m * Hsz + k0 + k]));
        }
        for (int i = tid; i < 256 * 32; i += 256) {
            int n = i >> 5, k = i & 31;
            Ws[n][k] = __uint_as_float(f2tf(W[(size_t)(ncol0 + n) * Hsz + k0 + k]));
        }
        __syncthreads();
#pragma unroll
        for (int kk = 0; kk < 32; kk += 8) {
            uint32_t bf[4][2];
#pragma unroll
            for (int nt = 0; nt < 4; nt++) {
                bf[nt][0] = __float_as_uint(Ws[wn0 + nt*8 + g][kk + cq]);
                bf[nt][1] = __float_as_uint(Ws[wn0 + nt*8 + g][kk + cq + 4]);
            }
#pragma unroll
            for (int mt = 0; mt < 6; mt++) {
                uint32_t a0 = __float_as_uint(As[mt*16 + g    ][kk + cq]);
                uint32_t a1 = __float_as_uint(As[mt*16 + g + 8][kk + cq]);
                uint32_t a2 = __float_as_uint(As[mt*16 + g    ][kk + cq + 4]);
                uint32_t a3 = __float_as_uint(As[mt*16 + g + 8][kk + cq + 4]);
#pragma unroll
                for (int nt = 0; nt < 4; nt++)
                    mma_tf32(acc[mt][nt], a0, a1, a2, a3, bf[nt][0], bf[nt][1]);
            }
        }
        __syncthreads();
    }

#pragma unroll
    for (int mt = 0; mt < 6; mt++) {
#pragma unroll
        for (int nt = 0; nt < 4; nt++) {
            int col = ncol0 + wn0 + nt*8 + cq*2;
            int r0 = mt*16 + g;
            float bx = bias[col], by = bias[col + 1];
            out[(size_t)r0 * Vz + col]           = acc[mt][nt][0] + bx;
            out[(size_t)r0 * Vz + col + 1]       = acc[mt][nt][1] + by;
            out[(size_t)(r0 + 8) * Vz + col]     = acc[mt][nt][2] + bx;
            out[(size_t)(r0 + 8) * Vz + col + 1] = acc[mt][nt][3] + by;
        }
    }
}

// ---------------- merged init ----------------
#define NQH (QLANES * Hqz)
#define NDH (DLANES * Hdz)
__global__ void k_init_all() {
    int i = blockIdx.x * blockDim.x + threadIdx.x;
    if (i < NQH) { g_qh0[i] = 0.f; g_qh1[i] = 0.f; g_qc[i] = 0.f; g_qrmax[i] = NEGF; }
    if (i < NDH) { g_dh0[i] = 0.f; g_dh1[i] = 0.f; g_dc[i] = 0.f; g_drmax[i] = NEGF; }
    if (i < Bz * Hsz) { g_sessH[i] = 0.f; g_sessC[i] = 0.f; }
    if (i == 0) { g_click = 0.f; g_dloss = 0.f; g_dcnt = 0.f; }
}

// ---------------- doc counting sort ----------------
__global__ void k_sortD(const int* __restrict__ rdl) {
    __shared__ int hist[DLz + 1];
    __shared__ int off[DLz + 1];
    int tid = threadIdx.x;
    for (int i = tid; i <= DLz; i += blockDim.x) hist[i] = 0;
    __syncthreads();
    for (int i = tid; i < NDOC; i += blockDim.x) atomicAdd(&hist[rdl[i]], 1);
    __syncthreads();
    if (tid == 0) {
        int acc = 0;
        for (int l = DLz; l >= 1; l--) { off[l] = acc; acc += hist[l]; }
    }
    __syncthreads();
    for (int t = tid; t < DLz; t += blockDim.x) {
        int cf = 0, cb = 0;
        for (int l = t + 1; l <= DLz; l++) cf += hist[l];
        for (int l = DLz - t; l <= DLz; l++) cb += hist[l];
        g_cntF[t] = cf;
        g_cntB[t] = cb;
    }
    __syncthreads();
    for (int i = tid; i < NDOC; i += blockDim.x) {
        int len = rdl[i];
        int pos = atomicAdd(&off[len], 1);
        g_permD[pos] = i;
        g_slenD[pos] = len;
        g_ilaneD[i] = pos;
    }
}

// ---------------- token tables ----------------
__global__ void k_qtok(const int* __restrict__ sq) {
    int i = blockIdx.x * blockDim.x + threadIdx.x;
    if (i >= QLz * QLANES) return;
    int t = i / QLANES, lane = i % QLANES;
    int n  = (lane < NQ) ? lane : lane - NQ;
    int tt = (lane < NQ) ? t : (QLz - 1 - t);
    g_qTok[i] = sq[n * QLz + tt];
}
__global__ void k_dtok(const int* __restrict__ rd) {
    int i = blockIdx.x * blockDim.x + threadIdx.x;
    if (i >= DLz * DLANES) return;
    int t = i / DLANES, lane = i % DLANES;
    int slane = (lane < NDOC) ? lane : lane - NDOC;
    int doc = g_permD[slane];
    int tt = (lane < NDOC) ? t : (DLz - 1 - t);
    g_dTok[i] = rd[doc * DLz + tt];
}
__global__ void k_dectok(const int* __restrict__ sq) {
    int i = blockIdx.x * blockDim.x + threadIdx.x;
    if (i >= TDEC * NDEC) return;
    int t = i / NDEC, n = i % NDEC;
    int b = n / (Sz - 1), s = n % (Sz - 1);
    const int* qrow = sq + (b * Sz + s + 1) * QLz;
    g_decTok[i] = qrow[t];
    g_decTgt[i] = qrow[t + 1];
}

// ---------------- encoder output assembly ----------------
__global__ void k_build_encq() {
    int i = blockIdx.x * blockDim.x + threadIdx.x;
    if (i >= NQ * 2 * Hqz) return;
    int n = i / (2 * Hqz), j = i % (2 * Hqz);
    g_encq[i] = (j < Hqz) ? g_qrmax[n * Hqz + j]
                          : g_qrmax[(NQ + n) * Hqz + (j - Hqz)];
}
__global__ void k_build_encd() {
    int i = blockIdx.x * blockDim.x + threadIdx.x;
    if (i >= NDOC * 2 * Hdz) return;
    int n = i / (2 * Hdz), j = i % (2 * Hdz);
    int lane = g_ilaneD[n];
    g_encd[i] = (j < Hdz) ? g_drmax[lane * Hdz + j]
                          : g_drmax[(NDOC + lane) * Hdz + (j - Hdz)];
}

// ---------------- reductions ----------------
__device__ __forceinline__ float blockReduceSum256(float v, float* sh) {
#pragma unroll
    for (int o = 16; o > 0; o >>= 1) v += __shfl_down_sync(0xffffffff, v, o);
    int lane = threadIdx.x & 31, w = threadIdx.x >> 5;
    if (lane == 0) sh[w] = v;
    __syncthreads();
    v = (threadIdx.x < 8) ? sh[threadIdx.x] : 0.f;
    if (w == 0) {
#pragma unroll
        for (int o = 4; o > 0; o >>= 1) v += __shfl_down_sync(0xffffffff, v, o);
    }
    __syncthreads();
    return v;
}

// ---------------- session score+BCE ----------------
__global__ void k_score_bce(const float* __restrict__ labels, int s) {
    __shared__ float comb[Hsz];
    __shared__ float red[8];
    int b = blockIdx.x;
    for (int j = threadIdx.x; j < Hsz; j += blockDim.x)
        comb[j] = tanhf(g_comb[b * Hsz + j]);
    __syncthreads();
    float local = 0.f;
    for (int d = 0; d < Dz; d++) {
        const float* ed = g_encd + (size_t)(((b * Sz + s) * Dz + d)) * (2 * Hdz);
        float p = 0.f;
        for (int j = threadIdx.x; j < 2 * Hdz; j += blockDim.x)
            p += comb[j] * ed[j];
        float score = blockReduceSum256(p, red);
        if (threadIdx.x == 0) {
            float lab = labels[(b * Sz + s) * Dz + d];
            local += fmaxf(score, 0.f) - score * lab + log1pf(expf(-fabsf(score)));
        }
    }
    if (threadIdx.x == 0) atomicAdd(&g_click, local);
}

// ---------------- session cell (unfused, tiny) ----------------
__global__ void k_sess_cell(int s) {
    int idx = blockIdx.x * blockDim.x + threadIdx.x;
    if (idx >= Bz * Hsz) return;
    int b = idx / Hsz, j = idx % Hsz;
    const float* g = g_sgates + (size_t)b * 4 * Hsz;
    float gi = g[j], gf = g[Hsz + j], gg = g[2 * Hsz + j], go = g[3 * Hsz + j];
    float cn = sigf(gf) * g_sessC[idx] + sigf(gi) * tanhf(gg);
    float hn = sigf(go) * tanhf(cn);
    g_sessH[idx] = hn; g_sessC[idx] = cn;
    g_histH[s * Bz * Hsz + idx] = hn;
    g_histC[s * Bz * Hsz + idx] = cn;
}

// ---------------- decoder init ----------------
__global__ void k_dec_init() {
    int idx = blockIdx.x * blockDim.x + threadIdx.x;
    if (idx >= NDEC * Hsz) return;
    int n = idx / Hsz, j = idx % Hsz;
    int b = n / (Sz - 1), s = n % (Sz - 1);
    g_decH0[idx] = g_histH[(s * Bz + b) * Hsz + j];
    g_decC[idx]  = g_histC[(s * Bz + b) * Hsz + j];
}

// ---------------- single-pass online-LSE NLL ----------------
__global__ void k_nll(const int* __restrict__ sql, int t) {
    __shared__ float shm[8], shs[8];
    int n = blockIdx.x;
    int b = n / (Sz - 1), s = n % (Sz - 1);
    int len = sql[b * Sz + s + 1];
    if (t >= len) return;
    const float* row = g_logits + (size_t)n * Vz;
    float m = -INFINITY, sm = 0.f;
    for (int j = threadIdx.x; j < Vz; j += blockDim.x) {
        float x = row[j];
        if (x > m) { sm = sm * expf(m - x) + 1.f; m = x; }
        else        sm += expf(x - m);
    }
#pragma unroll
    for (int o = 16; o > 0; o >>= 1) {
        float m2 = __shfl_down_sync(0xffffffff, m, o);
        float s2 = __shfl_down_sync(0xffffffff, sm, o);
        float M = fmaxf(m, m2);
        sm = sm * expf(m - M) + s2 * expf(m2 - M);
        m = M;
    }
    int lane = threadIdx.x & 31, w = threadIdx.x >> 5;
    if (lane == 0) { shm[w] = m; shs[w] = sm; }
    __syncthreads();
    if (threadIdx.x == 0) {
        m = shm[0]; sm = shs[0];
        for (int i = 1; i < 8; i++) {
            float M = fmaxf(m, shm[i]);
            sm = sm * expf(m - M) + shs[i] * expf(shm[i] - M);
            m = M;
        }
        float lse = m + logf(sm);
        int tgt = g_decTgt[t * NDEC + n];
        atomicAdd(&g_dloss, lse - row[tgt]);
        atomicAdd(&g_dcnt, 1.0f);
    }
}

__global__ void k_final(float* out) {
    float dec = (g_dcnt > 0.f) ? (g_dloss / g_dcnt) : 0.f;
    out[0] = g_click / (float)(Bz * Dz * Sz) + dec;
}

// ---------------- host helpers ----------------
static inline void big_store(const int* tok, const float* emb,
                             const float* W0, const float* W1, int ldw,
                             const float* b0, const float* b1,
                             float* C, int M, int N, int K,
                             int lanes, int half, int interleave,
                             const int* cntF, const int* cntB)
{
    dim3 grid(N / 128, (M + 127) / 128);
    gemm_big<<<grid, 256>>>(nullptr, 0, tok, emb, W0, W1, ldw, b0, b1,
                            C, N, M, N, K, lanes, half, MODE_STORE, interleave,
                            cntF, cntB, nullptr, nullptr, nullptr, nullptr, 0, 0);
}
static inline void big_cell(const float* hIn, const float* W0, const float* W1, int ldw,
                            const float* xg, int M, int N, int K,
                            int lanes, int half, const int* cntF, const int* cntB,
                            float* hOut, float* cState, float* rmax,
                            const int* lens, int T, int t)
{
    dim3 grid(N / 128, (M + 127) / 128);
    gemm_big<<<grid, 256>>>(hIn, K, nullptr, nullptr, W0, W1, ldw, nullptr, nullptr,
                            (float*)xg, N, M, N, K, lanes, half, MODE_CELL, 1,
                            cntF, cntB, hOut, cState, rmax, lens, T, t);
}
static inline void small_mode(const float* A, int lda, const float* W0, const float* W1,
                              int ldw, const float* b0, const float* b1,
                              float* C, int ldc, int M, int N, int K,
                              int lanes, int half, int mode, int interleave)
{
    dim3 grid(N / 64, (M + 63) / 64);
    gemm_small<<<grid, 256>>>(A, lda, nullptr, nullptr, W0, W1, ldw, b0, b1,
                              C, ldc, M, N, K, lanes, half, mode, interleave,
                              nullptr, nullptr, nullptr, nullptr, 0, 0);
}
static inline void small_cell(const float* hIn, const float* W0, const float* W1, int ldw,
                              const float* xg, int M, int N, int K,
                              int lanes, int half,
                              float* hOut, float* cState, float* rmax,
                              const int* lens, int T, int t)
{
    dim3 grid(N / 64, (M + 63) / 64);
    gemm_small<<<grid, 256>>>(hIn, K, nullptr, nullptr, W0, W1, ldw, nullptr, nullptr,
                              (float*)xg, N, M, N, K, lanes, half, MODE_CELL, 1,
                              hOut, cState, rmax, lens, T, t);
}

#define GETSYM(var, sym) do { void* p_; cudaGetSymbolAddress(&p_, sym); var = (decltype(var))p_; } while (0)

extern "C" void kernel_launch(void* const* d_in, const int* in_sizes, int n_in,
                              void* d_out, int out_size)
{
    (void)in_sizes; (void)n_in; (void)out_size;
    const int*   sq     = (const int*)d_in[0];
    const int*   sql    = (const int*)d_in[1];
    const int*   rd     = (const int*)d_in[2];
    const int*   rdl    = (const int*)d_in[3];
    const float* labels = (const float*)d_in[4];
    const float* emb    = (const float*)d_in[5];
    const float* qWihf  = (const float*)d_in[6];
    const float* qWhhf  = (const float*)d_in[7];
    const float* qbf    = (const float*)d_in[8];
    const float* qWihb  = (const float*)d_in[9];
    const float* qWhhb  = (const float*)d_in[10];
    const float* qbb    = (const float*)d_in[11];
    const float* dWihf  = (const float*)d_in[12];
    const float* dWhhf  = (const float*)d_in[13];
    const float* dbf    = (const float*)d_in[14];
    const float* dWihb  = (const float*)d_in[15];
    const float* dWhhb  = (const float*)d_in[16];
    const float* dbb    = (const float*)d_in[17];
    const float* sWih   = (const float*)d_in[18];
    const float* sWhh   = (const float*)d_in[19];
    const float* sb     = (const float*)d_in[20];
    const float* projW  = (const float*)d_in[21];
    const float* projb  = (const float*)d_in[22];
    const float* decWih = (const float*)d_in[23];
    const float* decWhh = (const float*)d_in[24];
    const float* decb   = (const float*)d_in[25];
    const float* outW   = (const float*)d_in[26];
    const float* outb   = (const float*)d_in[27];

    float *qGates, *dGates, *decGates, *logits;
    float *qh[2], *qc, *qrmax, *dh[2], *dc, *drmax, *encq, *sessH;
    float *decH[2], *decC, *comb, *sgates;
    int *qTok, *dTok, *decTok, *cntF, *cntB, *slenD;
    GETSYM(qGates, g_qGates);     GETSYM(dGates, g_dGates);
    GETSYM(decGates, g_decGates); GETSYM(logits, g_logits);
    GETSYM(qh[0], g_qh0); GETSYM(qh[1], g_qh1);
    GETSYM(qc, g_qc); GETSYM(qrmax, g_qrmax);
    GETSYM(dh[0], g_dh0); GETSYM(dh[1], g_dh1);
    GETSYM(dc, g_dc); GETSYM(drmax, g_drmax);
    GETSYM(encq, g_encq); GETSYM(sessH, g_sessH);
    GETSYM(decH[0], g_decH0); GETSYM(decH[1], g_decH1); GETSYM(decC, g_decC);
    GETSYM(comb, g_comb); GETSYM(sgates, g_sgates);
    GETSYM(qTok, g_qTok); GETSYM(dTok, g_dTok); GETSYM(decTok, g_decTok);
    GETSYM(cntF, g_cntF); GETSYM(cntB, g_cntB); GETSYM(slenD, g_slenD);

    const int TPB = 256;
    k_init_all<<<(NDH + TPB - 1) / TPB, TPB>>>();
    k_sortD<<<1, 256>>>(rdl);
    k_qtok<<<(QLz * QLANES + TPB - 1) / TPB, TPB>>>(sq);
    k_dtok<<<(DLz * DLANES + TPB - 1) / TPB, TPB>>>(rd);
    k_dectok<<<(TDEC * NDEC + TPB - 1) / TPB, TPB>>>(sq);

    // ---- x-part gates (gather GEMMs, interleaved gate layout) ----
    big_store(qTok, emb, qWihf, qWihb, Ez, qbf, qbb,
              qGates, QLz * QLANES, 4 * Hqz, Ez, QLANES, NQ, 1, nullptr, nullptr);
    big_store(dTok, emb, dWihf, dWihb, Ez, dbf, dbb,
              dGates, DLz * DLANES, 4 * Hdz, Ez, DLANES, NDOC, 1, cntF, cntB);
    big_store(decTok, emb, decWih, decWih, Ez, decb, decb,
              decGates, TDEC * NDEC, 4 * Hsz, Ez, TDEC * NDEC, TDEC * NDEC, 1,
              nullptr, nullptr);

    // ---- query BiLSTM: fused recurrence+cell ----
    for (int t = 0; t < QLz; t++) {
        const float* xg = qGates + (size_t)t * QLANES * 4 * Hqz;
        small_cell(qh[t & 1], qWhhf, qWhhb, Hqz, xg,
                   QLANES, 4 * Hqz, Hqz, QLANES, NQ,
                   qh[(t + 1) & 1], qc, qrmax, sql, QLz, t);
    }

    // ---- doc BiLSTM: fused recurrence+cell with active-count skip ----
    for (int t = 0; t < DLz; t++) {
        const float* xg = dGates + (size_t)t * DLANES * 4 * Hdz;
        big_cell(dh[t & 1], dWhhf, dWhhb, Hdz, xg,
                 DLANES, 4 * Hdz, Hdz, DLANES, NDOC, cntF + t, cntB + t,
                 dh[(t + 1) & 1], dc, drmax, slenD, DLz, t);
    }

    k_build_encq<<<(NQ * 2 * Hqz + TPB - 1) / TPB, TPB>>>();
    k_build_encd<<<(NDOC * 2 * Hdz + TPB - 1) / TPB, TPB>>>();

    // ---- session loop (small, unfused) ----
    for (int s = 0; s < Sz; s++) {
        small_mode(encq + s * (2 * Hqz), Sz * 2 * Hqz, projW, projW,
                   2 * Hqz + Hsz, projb, projb,
                   comb, Hsz, Bz, Hsz, 2 * Hqz, Bz, Bz, MODE_STORE, 0);
        small_mode(sessH, Hsz, projW + 2 * Hqz, projW + 2 * Hqz,
                   2 * Hqz + Hsz, nullptr, nullptr,
                   comb, Hsz, Bz, Hsz, Hsz, Bz, Bz, MODE_ACC, 0);
        k_score_bce<<<Bz, 256>>>(labels, s);
        small_mode(encq + s * (2 * Hqz), Sz * 2 * Hqz, sWih, sWih,
                   2 * Hqz, sb, sb,
                   sgates, 4 * Hsz, Bz, 4 * Hsz, 2 * Hqz, Bz, Bz, MODE_STORE, 0);
        small_mode(sessH, Hsz, sWhh, sWhh, Hsz, nullptr, nullptr,
                   sgates, 4 * Hsz, Bz, 4 * Hsz, Hsz, Bz, Bz, MODE_ACC, 0);
        k_sess_cell<<<(Bz * Hsz + TPB - 1) / TPB, TPB>>>(s);
    }

    // ---- decoder: fused cell + tf32 logits + online NLL ----
    k_dec_init<<<(NDEC * Hsz + TPB - 1) / TPB, TPB>>>();
    for (int t = 0; t < TDEC; t++) {
        const float* xg = decGates + (size_t)t * NDEC * 4 * Hsz;
        small_cell(decH[t & 1], decWhh, decWhh, Hsz, xg,
                   NDEC, 4 * Hsz, Hsz, NDEC, NDEC,
                   decH[(t + 1) & 1], decC, nullptr, nullptr, 0, 0);
        k_logits_tf32<<<Vz / 256, 256>>>(decH[(t + 1) & 1], outW, outb, logits);
        k_nll<<<NDEC, 256>>>(sql, t);
    }

    k_final<<<1, 1>>>((float*)d_out);
}

// round 7
// speedup vs baseline: 1.0093x; 1.0093x over previous
#include <cuda_runtime.h>
#include <math.h>
#include <stdint.h>

// ---------------- problem constants ----------------
#define Bz   32
#define Sz   4
#define QLz  12
#define Dz   10
#define DLz  40
#define Vz   32000
#define Ez   256
#define Hqz  256
#define Hdz  256
#define Hsz  512

#define NQ     128
#define NDOC   1280
#define QLANES 256
#define DLANES 2560
#define NDEC   96
#define TDEC   11
#define NEGF   (-1000000000.0f)

#define MODE_STORE 0
#define MODE_ACC   1
#define MODE_CELL  2

// ---------------- scratch ----------------
__device__ float g_qGates[QLz * QLANES * 4 * Hqz];          // interleaved
__device__ float g_dGates[DLz * DLANES * 4 * Hdz];          // interleaved
__device__ float g_decGates[TDEC * NDEC * 4 * Hsz];         // interleaved
__device__ float g_logits[NDEC * Vz];

__device__ float g_qh0[QLANES * Hqz], g_qh1[QLANES * Hqz];
__device__ float g_qc[QLANES * Hqz], g_qrmax[QLANES * Hqz];
__device__ float g_dh0[DLANES * Hdz], g_dh1[DLANES * Hdz];
__device__ float g_dc[DLANES * Hdz], g_drmax[DLANES * Hdz];
__device__ float g_encq[NQ * 2 * Hqz];
__device__ float g_encd[NDOC * 2 * Hdz];
__device__ float g_sessH[Bz * Hsz], g_sessC[Bz * Hsz];
__device__ float g_histH[Sz * Bz * Hsz], g_histC[Sz * Bz * Hsz];
__device__ float g_comb[Bz * Hsz];
__device__ float g_sgates[Bz * 4 * Hsz];
__device__ float g_decH0[NDEC * Hsz], g_decH1[NDEC * Hsz], g_decC[NDEC * Hsz];

__device__ int g_qTok[QLz * QLANES];
__device__ int g_dTok[DLz * DLANES];
__device__ int g_decTok[TDEC * NDEC];
__device__ int g_decTgt[TDEC * NDEC];

__device__ int g_permD[NDOC];
__device__ int g_ilaneD[NDOC];
__device__ int g_slenD[NDOC];
__device__ int g_cntF[DLz];
__device__ int g_cntB[DLz];

__device__ float g_click, g_dloss, g_dcnt;

__device__ __forceinline__ float sigf(float x) { return 1.0f / (1.0f + expf(-x)); }

__device__ __forceinline__ uint32_t f2tf(float f) {
    uint32_t u;
    asm("cvt.rna.tf32.f32 %0, %1;" : "=r"(u) : "f"(f));
    return u;
}
__device__ __forceinline__ void mma_tf32(float* d, uint32_t a0, uint32_t a1,
                                         uint32_t a2, uint32_t a3,
                                         uint32_t b0, uint32_t b1) {
    asm volatile(
        "mma.sync.aligned.m16n8k8.row.col.f32.tf32.tf32.f32 "
        "{%0,%1,%2,%3}, {%4,%5,%6,%7}, {%8,%9}, {%0,%1,%2,%3};\n"
        : "+f"(d[0]), "+f"(d[1]), "+f"(d[2]), "+f"(d[3])
        : "r"(a0), "r"(a1), "r"(a2), "r"(a3), "r"(b0), "r"(b1));
}

// weight row mapping for interleaved gate layout: out col c -> orig W row
__device__ __forceinline__ int wmap(int c, int Hn) {
    return (c & 3) * Hn + (c >> 2);
}

// =======================================================================
// TF32 GEMM: 128x128 tile, 256 thr = 8 warps (warp&1 -> 64 rows, warp>>1 -> 32 cols)
// C[M][N] (+)= Arow(r) . Wrow(wmap(n))  [gates ALWAYS interleaved]
// MODE_STORE: gather (tok/emb) -> C = acc + bias (bias in original i|f|g|o layout)
// MODE_CELL : A = hIn; epilogue fuses LSTM cell using xgates in C
// Dual weights at 128-row tile granularity; optional cntF/cntB skip.
// Requires N%128==0, K%16==0.
// =======================================================================
__global__ __launch_bounds__(256) void gemm_tf32(
    const float* __restrict__ A, int lda,
    const int* __restrict__ tok, const float* __restrict__ emb,
    const float* __restrict__ W0, const float* __restrict__ W1, int ldw,
    const float* __restrict__ b0, const float* __restrict__ b1,
    float* __restrict__ C, int ldc,
    int M, int N, int K,
    int lanes, int halfLanes, int mode,
    const int* __restrict__ cntF, const int* __restrict__ cntB,
    float* __restrict__ hOut, float* __restrict__ cState,
    float* __restrict__ rmax, const int* __restrict__ lens, int T, int t)
{
    const int row0 = blockIdx.y * 128;
    const int col0 = blockIdx.x * 128;
    const int Hn = N >> 2;

    const int lane0 = row0 % lanes;
    if (cntF) {
        const int tt = row0 / lanes;
        if (lane0 < halfLanes) { if (lane0 >= cntF[tt]) return; }
        else                   { if (lane0 - halfLanes >= cntB[tt]) return; }
    }
    const int dir = (lane0 < halfLanes) ? 0 : 1;
    const float* W    = dir ? W1 : W0;
    const float* bias = dir ? b1 : b0;

    __shared__ float As[128][17];   // [row][k]
    __shared__ float Ws[128][17];   // [out-col][k]

    const int tid  = threadIdx.x;
    const int warp = tid >> 5, lane = tid & 31;
    const int g  = lane >> 2, cq = lane & 3;
    const int wm0 = (warp & 1) * 64;
    const int wn0 = (warp >> 1) * 32;

    const int lr = tid >> 1;          // 0..127
    const int lk = (tid & 1) << 3;    // 0 or 8

    const int ar = row0 + lr;
    const bool aok = (ar < M);
    const float* arow;
    if (tok) arow = emb + (size_t)tok[aok ? ar : 0] * K;
    else     arow = A + (size_t)(aok ? ar : 0) * lda;
    const float* wrow = W + (size_t)wmap(col0 + lr, Hn) * ldw;

    float acc[4][4][4];
#pragma unroll
    for (int i = 0; i < 4; i++)
#pragma unroll
        for (int j = 0; j < 4; j++)
#pragma unroll
            for (int v = 0; v < 4; v++) acc[i][j][v] = 0.0f;

    float4 av0, av1, wv0, wv1;
    {
        av0 = aok ? *(const float4*)(arow + lk)     : make_float4(0,0,0,0);
        av1 = aok ? *(const float4*)(arow + lk + 4) : make_float4(0,0,0,0);
        wv0 = *(const float4*)(wrow + lk);
        wv1 = *(const float4*)(wrow + lk + 4);
        As[lr][lk+0]=__uint_as_float(f2tf(av0.x)); As[lr][lk+1]=__uint_as_float(f2tf(av0.y));
        As[lr][lk+2]=__uint_as_float(f2tf(av0.z)); As[lr][lk+3]=__uint_as_float(f2tf(av0.w));
        As[lr][lk+4]=__uint_as_float(f2tf(av1.x)); As[lr][lk+5]=__uint_as_float(f2tf(av1.y));
        As[lr][lk+6]=__uint_as_float(f2tf(av1.z)); As[lr][lk+7]=__uint_as_float(f2tf(av1.w));
        Ws[lr][lk+0]=__uint_as_float(f2tf(wv0.x)); Ws[lr][lk+1]=__uint_as_float(f2tf(wv0.y));
        Ws[lr][lk+2]=__uint_as_float(f2tf(wv0.z)); Ws[lr][lk+3]=__uint_as_float(f2tf(wv0.w));
        Ws[lr][lk+4]=__uint_as_float(f2tf(wv1.x)); Ws[lr][lk+5]=__uint_as_float(f2tf(wv1.y));
        Ws[lr][lk+6]=__uint_as_float(f2tf(wv1.z)); Ws[lr][lk+7]=__uint_as_float(f2tf(wv1.w));
    }
    __syncthreads();

    for (int k0 = 0; k0 < K; k0 += 16) {
        const bool more = (k0 + 16) < K;
        if (more) {
            const int kn = k0 + 16 + lk;
            av0 = aok ? *(const float4*)(arow + kn)     : make_float4(0,0,0,0);
            av1 = aok ? *(const float4*)(arow + kn + 4) : make_float4(0,0,0,0);
            wv0 = *(const float4*)(wrow + kn);
            wv1 = *(const float4*)(wrow + kn + 4);
        }
#pragma unroll
        for (int kk = 0; kk < 16; kk += 8) {
            uint32_t bf[4][2];
#pragma unroll
            for (int nt = 0; nt < 4; nt++) {
                bf[nt][0] = __float_as_uint(Ws[wn0 + nt*8 + g][kk + cq]);
                bf[nt][1] = __float_as_uint(Ws[wn0 + nt*8 + g][kk + cq + 4]);
            }
#pragma unroll
            for (int mt = 0; mt < 4; mt++) {
                uint32_t a0 = __float_as_uint(As[wm0 + mt*16 + g    ][kk + cq]);
                uint32_t a1 = __float_as_uint(As[wm0 + mt*16 + g + 8][kk + cq]);
                uint32_t a2 = __float_as_uint(As[wm0 + mt*16 + g    ][kk + cq + 4]);
                uint32_t a3 = __float_as_uint(As[wm0 + mt*16 + g + 8][kk + cq + 4]);
#pragma unroll
                for (int nt = 0; nt < 4; nt++)
                    mma_tf32(acc[mt][nt], a0, a1, a2, a3, bf[nt][0], bf[nt][1]);
            }
        }
        __syncthreads();
        if (more) {
            As[lr][lk+0]=__uint_as_float(f2tf(av0.x)); As[lr][lk+1]=__uint_as_float(f2tf(av0.y));
            As[lr][lk+2]=__uint_as_float(f2tf(av0.z)); As[lr][lk+3]=__uint_as_float(f2tf(av0.w));
            As[lr][lk+4]=__uint_as_float(f2tf(av1.x)); As[lr][lk+5]=__uint_as_float(f2tf(av1.y));
            As[lr][lk+6]=__uint_as_float(f2tf(av1.z)); As[lr][lk+7]=__uint_as_float(f2tf(av1.w));
            Ws[lr][lk+0]=__uint_as_float(f2tf(wv0.x)); Ws[lr][lk+1]=__uint_as_float(f2tf(wv0.y));
            Ws[lr][lk+2]=__uint_as_float(f2tf(wv0.z)); Ws[lr][lk+3]=__uint_as_float(f2tf(wv0.w));
            Ws[lr][lk+4]=__uint_as_float(f2tf(wv1.x)); Ws[lr][lk+5]=__uint_as_float(f2tf(wv1.y));
            Ws[lr][lk+6]=__uint_as_float(f2tf(wv1.z)); Ws[lr][lk+7]=__uint_as_float(f2tf(wv1.w));
            __syncthreads();
        }
    }

    // D mapping (proven in R4 logits kernel):
    //   acc[mt][nt][0] -> (row wm0+mt*16+g,   col wn0+nt*8+2cq)
    //   acc[mt][nt][1] -> (row wm0+mt*16+g,   col wn0+nt*8+2cq+1)
    //   acc[mt][nt][2] -> (row wm0+mt*16+g+8, col ...2cq)
    //   acc[mt][nt][3] -> (row ...g+8,        col ...2cq+1)

    if (mode == MODE_CELL) {
#pragma unroll
        for (int mt = 0; mt < 4; mt++) {
#pragma unroll
            for (int nt = 0; nt < 4; nt++) {
                // exchange col-pairs with lane^1 to assemble i/f/g/o quadruples
                float p0 = __shfl_xor_sync(0xffffffff, acc[mt][nt][0], 1);
                float p1 = __shfl_xor_sync(0xffffffff, acc[mt][nt][1], 1);
                float p2 = __shfl_xor_sync(0xffffffff, acc[mt][nt][2], 1);
                float p3 = __shfl_xor_sync(0xffffffff, acc[mt][nt][3], 1);
                if ((cq & 1) == 0) {
                    const int cc = col0 + wn0 + nt*8 + 2*cq;  // quadruple base (cc%4==0)
                    const int j  = cc >> 2;
#pragma unroll
                    for (int half = 0; half < 2; half++) {
                        const int r = row0 + wm0 + mt*16 + g + half*8;
                        if (r >= M) continue;
                        bool valid = true;
                        if (lens) {
                            int n = (r < halfLanes) ? r : r - halfLanes;
                            int len = lens[n];
                            valid = (r < halfLanes) ? (t < len) : (t >= T - len);
                        }
                        if (!valid) continue;
                        float gi, gf, gg, go;
                        if (half == 0) { gi = acc[mt][nt][0]; gf = acc[mt][nt][1]; gg = p0; go = p1; }
                        else           { gi = acc[mt][nt][2]; gf = acc[mt][nt][3]; gg = p2; go = p3; }
                        float4 xg = *(const float4*)(C + (size_t)r * ldc + cc);
                        gi += xg.x; gf += xg.y; gg += xg.z; go += xg.w;
                        float cp = cState[(size_t)r * Hn + j];
                        float cn = sigf(gf) * cp + sigf(gi) * tanhf(gg);
                        float hn = sigf(go) * tanhf(cn);
                        cState[(size_t)r * Hn + j] = cn;
                        hOut[(size_t)r * Hn + j] = hn;
                        if (rmax) {
                            float rm = rmax[(size_t)r * Hn + j];
                            rmax[(size_t)r * Hn + j] = (hn > rm) ? hn : rm;
                        }
                    }
                }
            }
        }
        return;
    }

    // MODE_STORE (gather): C = acc + bias (interleaved mapping)
#pragma unroll
    for (int mt = 0; mt < 4; mt++) {
#pragma unroll
        for (int nt = 0; nt < 4; nt++) {
            const int cc = col0 + wn0 + nt*8 + 2*cq;
            float bx = bias ? bias[wmap(cc, Hn)] : 0.f;
            float by = bias ? bias[wmap(cc + 1, Hn)] : 0.f;
            const int r0 = row0 + wm0 + mt*16 + g;
            if (r0 < M) {
                float2 v = make_float2(acc[mt][nt][0] + bx, acc[mt][nt][1] + by);
                *(float2*)(C + (size_t)r0 * ldc + cc) = v;
            }
            const int r1 = r0 + 8;
            if (r1 < M) {
                float2 v = make_float2(acc[mt][nt][2] + bx, acc[mt][nt][3] + by);
                *(float2*)(C + (size_t)r1 * ldc + cc) = v;
            }
        }
    }
}

// =======================================================================
// SMALL fp32 GEMM: 64x64 tile (session path only; no interleave)
// =======================================================================
__global__ __launch_bounds__(256) void gemm_small(
    const float* __restrict__ A, int lda,
    const float* __restrict__ W, int ldw,
    const float* __restrict__ bias,
    float* __restrict__ C, int ldc,
    int M, int N, int K, int mode)
{
    __shared__ float As[16][65];
    __shared__ float Ws[16][65];

    const int tid  = threadIdx.x;
    const int row0 = blockIdx.y * 64;
    const int col0 = blockIdx.x * 64;

    const int lr = tid >> 2;
    const int lk = (tid & 3) << 2;
    const int ty4 = (tid >> 4) << 2;
    const int tx4 = (tid & 15) << 2;

    float acc[4][4];
#pragma unroll
    for (int i = 0; i < 4; i++)
#pragma unroll
        for (int j = 0; j < 4; j++) acc[i][j] = 0.0f;

    const int ar = row0 + lr;
    const float* arow = A + (size_t)((ar < M) ? ar : 0) * lda;
    const float* wrow = W + (size_t)(col0 + lr) * ldw;
    const bool arow_ok = (ar < M);

    for (int k0 = 0; k0 < K; k0 += 16) {
        float4 av = *(const float4*)(arow + k0 + lk);
        if (!arow_ok) av = make_float4(0.f, 0.f, 0.f, 0.f);
        float4 wv = *(const float4*)(wrow + k0 + lk);
        As[lk + 0][lr] = av.x; As[lk + 1][lr] = av.y;
        As[lk + 2][lr] = av.z; As[lk + 3][lr] = av.w;
        Ws[lk + 0][lr] = wv.x; Ws[lk + 1][lr] = wv.y;
        Ws[lk + 2][lr] = wv.z; Ws[lk + 3][lr] = wv.w;
        __syncthreads();
#pragma unroll
        for (int k = 0; k < 16; k++) {
            float a0 = As[k][ty4 + 0], a1 = As[k][ty4 + 1];
            float a2 = As[k][ty4 + 2], a3 = As[k][ty4 + 3];
            float w0 = Ws[k][tx4 + 0], w1 = Ws[k][tx4 + 1];
            float w2 = Ws[k][tx4 + 2], w3 = Ws[k][tx4 + 3];
            acc[0][0] += a0 * w0; acc[0][1] += a0 * w1; acc[0][2] += a0 * w2; acc[0][3] += a0 * w3;
            acc[1][0] += a1 * w0; acc[1][1] += a1 * w1; acc[1][2] += a1 * w2; acc[1][3] += a1 * w3;
            acc[2][0] += a2 * w0; acc[2][1] += a2 * w1; acc[2][2] += a2 * w2; acc[2][3] += a2 * w3;
            acc[3][0] += a3 * w0; acc[3][1] += a3 * w1; acc[3][2] += a3 * w2; acc[3][3] += a3 * w3;
        }
        __syncthreads();
    }

#pragma unroll
    for (int i = 0; i < 4; i++) {
        int r = row0 + ty4 + i;
        if (r >= M) continue;
        float* cp = C + (size_t)r * ldc + col0 + tx4;
#pragma unroll
        for (int jj = 0; jj < 4; jj++) {
            float v = acc[i][jj];
            if (mode == MODE_ACC) v += cp[jj];
            else if (bias) v += bias[col0 + tx4 + jj];
            cp[jj] = v;
        }
    }
}

// =======================================================================
// tf32 logits GEMM (unchanged from R4, proven)
// =======================================================================
__global__ __launch_bounds__(256) void k_logits_tf32(
    const float* __restrict__ Hc, const float* __restrict__ W,
    const float* __restrict__ bias, float* __restrict__ out)
{
    __shared__ float As[96][33];
    __shared__ float Ws[256][33];
    const int tid = threadIdx.x;
    const int warp = tid >> 5, lane = tid & 31;
    const int g = lane >> 2, cq = lane & 3;
    const int ncol0 = blockIdx.x * 256;
    const int wn0 = warp * 32;

    float acc[6][4][4];
#pragma unroll
    for (int m = 0; m < 6; m++)
#pragma unroll
        for (int n = 0; n < 4; n++)
#pragma unroll
            for (int v = 0; v < 4; v++) acc[m][n][v] = 0.0f;

    for (int k0 = 0; k0 < Hsz; k0 += 32) {
        for (int i = tid; i < 96 * 32; i += 256) {
            int m = i >> 5, k = i & 31;
            As[m][k] = __uint_as_float(f2tf(Hc[m * Hsz + k0 + k]));
        }
        for (int i = tid; i < 256 * 32; i += 256) {
            int n = i >> 5, k = i & 31;
            Ws[n][k] = __uint_as_float(f2tf(W[(size_t)(ncol0 + n) * Hsz + k0 + k]));
        }
        __syncthreads();
#pragma unroll
        for (int kk = 0; kk < 32; kk += 8) {
            uint32_t bf[4][2];
#pragma unroll
            for (int nt = 0; nt < 4; nt++) {
                bf[nt][0] = __float_as_uint(Ws[wn0 + nt*8 + g][kk + cq]);
                bf[nt][1] = __float_as_uint(Ws[wn0 + nt*8 + g][kk + cq + 4]);
            }
#pragma unroll
            for (int mt = 0; mt < 6; mt++) {
                uint32_t a0 = __float_as_uint(As[mt*16 + g    ][kk + cq]);
                uint32_t a1 = __float_as_uint(As[mt*16 + g + 8][kk + cq]);
                uint32_t a2 = __float_as_uint(As[mt*16 + g    ][kk + cq + 4]);
                uint32_t a3 = __float_as_uint(As[mt*16 + g + 8][kk + cq + 4]);
#pragma unroll
                for (int nt = 0; nt < 4; nt++)
                    mma_tf32(acc[mt][nt], a0, a1, a2, a3, bf[nt][0], bf[nt][1]);
            }
        }
        __syncthreads();
    }

#pragma unroll
    for (int mt = 0; mt < 6; mt++) {
#pragma unroll
        for (int nt = 0; nt < 4; nt++) {
            int col = ncol0 + wn0 + nt*8 + cq*2;
            int r0 = mt*16 + g;
            float bx = bias[col], by = bias[col + 1];
            out[(size_t)r0 * Vz + col]           = acc[mt][nt][0] + bx;
            out[(size_t)r0 * Vz + col + 1]       = acc[mt][nt][1] + by;
            out[(size_t)(r0 + 8) * Vz + col]     = acc[mt][nt][2] + bx;
            out[(size_t)(r0 + 8) * Vz + col + 1] = acc[mt][nt][3] + by;
        }
    }
}

// ---------------- merged init ----------------
#define NQH (QLANES * Hqz)
#define NDH (DLANES * Hdz)
__global__ void k_init_all() {
    int i = blockIdx.x * blockDim.x + threadIdx.x;
    if (i < NQH) { g_qh0[i] = 0.f; g_qh1[i] = 0.f; g_qc[i] = 0.f; g_qrmax[i] = NEGF; }
    if (i < NDH) { g_dh0[i] = 0.f; g_dh1[i] = 0.f; g_dc[i] = 0.f; g_drmax[i] = NEGF; }
    if (i < Bz * Hsz) { g_sessH[i] = 0.f; g_sessC[i] = 0.f; }
    if (i == 0) { g_click = 0.f; g_dloss = 0.f; g_dcnt = 0.f; }
}

// ---------------- doc counting sort ----------------
__global__ void k_sortD(const int* __restrict__ rdl) {
    __shared__ int hist[DLz + 1];
    __shared__ int off[DLz + 1];
    int tid = threadIdx.x;
    for (int i = tid; i <= DLz; i += blockDim.x) hist[i] = 0;
    __syncthreads();
    for (int i = tid; i < NDOC; i += blockDim.x) atomicAdd(&hist[rdl[i]], 1);
    __syncthreads();
    if (tid == 0) {
        int acc = 0;
        for (int l = DLz; l >= 1; l--) { off[l] = acc; acc += hist[l]; }
    }
    __syncthreads();
    for (int t = tid; t < DLz; t += blockDim.x) {
        int cf = 0, cb = 0;
        for (int l = t + 1; l <= DLz; l++) cf += hist[l];
        for (int l = DLz - t; l <= DLz; l++) cb += hist[l];
        g_cntF[t] = cf;
        g_cntB[t] = cb;
    }
    __syncthreads();
    for (int i = tid; i < NDOC; i += blockDim.x) {
        int len = rdl[i];
        int pos = atomicAdd(&off[len], 1);
        g_permD[pos] = i;
        g_slenD[pos] = len;
        g_ilaneD[i] = pos;
    }
}

// ---------------- token tables ----------------
__global__ void k_qtok(const int* __restrict__ sq) {
    int i = blockIdx.x * blockDim.x + threadIdx.x;
    if (i >= QLz * QLANES) return;
    int t = i / QLANES, lane = i % QLANES;
    int n  = (lane < NQ) ? lane : lane - NQ;
    int tt = (lane < NQ) ? t : (QLz - 1 - t);
    g_qTok[i] = sq[n * QLz + tt];
}
__global__ void k_dtok(const int* __restrict__ rd) {
    int i = blockIdx.x * blockDim.x + threadIdx.x;
    if (i >= DLz * DLANES) return;
    int t = i / DLANES, lane = i % DLANES;
    int slane = (lane < NDOC) ? lane : lane - NDOC;
    int doc = g_permD[slane];
    int tt = (lane < NDOC) ? t : (DLz - 1 - t);
    g_dTok[i] = rd[doc * DLz + tt];
}
__global__ void k_dectok(const int* __restrict__ sq) {
    int i = blockIdx.x * blockDim.x + threadIdx.x;
    if (i >= TDEC * NDEC) return;
    int t = i / NDEC, n = i % NDEC;
    int b = n / (Sz - 1), s = n % (Sz - 1);
    const int* qrow = sq + (b * Sz + s + 1) * QLz;
    g_decTok[i] = qrow[t];
    g_decTgt[i] = qrow[t + 1];
}

// ---------------- encoder output assembly ----------------
__global__ void k_build_encq() {
    int i = blockIdx.x * blockDim.x + threadIdx.x;
    if (i >= NQ * 2 * Hqz) return;
    int n = i / (2 * Hqz), j = i % (2 * Hqz);
    g_encq[i] = (j < Hqz) ? g_qrmax[n * Hqz + j]
                          : g_qrmax[(NQ + n) * Hqz + (j - Hqz)];
}
__global__ void k_build_encd() {
    int i = blockIdx.x * blockDim.x + threadIdx.x;
    if (i >= NDOC * 2 * Hdz) return;
    int n = i / (2 * Hdz), j = i % (2 * Hdz);
    int lane = g_ilaneD[n];
    g_encd[i] = (j < Hdz) ? g_drmax[lane * Hdz + j]
                          : g_drmax[(NDOC + lane) * Hdz + (j - Hdz)];
}

// ---------------- reductions ----------------
__device__ __forceinline__ float blockReduceSum256(float v, float* sh) {
#pragma unroll
    for (int o = 16; o > 0; o >>= 1) v += __shfl_down_sync(0xffffffff, v, o);
    int lane = threadIdx.x & 31, w = threadIdx.x >> 5;
    if (lane == 0) sh[w] = v;
    __syncthreads();
    v = (threadIdx.x < 8) ? sh[threadIdx.x] : 0.f;
    if (w == 0) {
#pragma unroll
        for (int o = 4; o > 0; o >>= 1) v += __shfl_down_sync(0xffffffff, v, o);
    }
    __syncthreads();
    return v;
}

// ---------------- session score+BCE ----------------
__global__ void k_score_bce(const float* __restrict__ labels, int s) {
    __shared__ float comb[Hsz];
    __shared__ float red[8];
    int b = blockIdx.x;
    for (int j = threadIdx.x; j < Hsz; j += blockDim.x)
        comb[j] = tanhf(g_comb[b * Hsz + j]);
    __syncthreads();
    float local = 0.f;
    for (int d = 0; d < Dz; d++) {
        const float* ed = g_encd + (size_t)(((b * Sz + s) * Dz + d)) * (2 * Hdz);
        float p = 0.f;
        for (int j = threadIdx.x; j < 2 * Hdz; j += blockDim.x)
            p += comb[j] * ed[j];
        float score = blockReduceSum256(p, red);
        if (threadIdx.x == 0) {
            float lab = labels[(b * Sz + s) * Dz + d];
            local += fmaxf(score, 0.f) - score * lab + log1pf(expf(-fabsf(score)));
        }
    }
    if (threadIdx.x == 0) atomicAdd(&g_click, local);
}

// ---------------- session cell ----------------
__global__ void k_sess_cell(int s) {
    int idx = blockIdx.x * blockDim.x + threadIdx.x;
    if (idx >= Bz * Hsz) return;
    int b = idx / Hsz, j = idx % Hsz;
    const float* g = g_sgates + (size_t)b * 4 * Hsz;
    float gi = g[j], gf = g[Hsz + j], gg = g[2 * Hsz + j], go = g[3 * Hsz + j];
    float cn = sigf(gf) * g_sessC[idx] + sigf(gi) * tanhf(gg);
    float hn = sigf(go) * tanhf(cn);
    g_sessH[idx] = hn; g_sessC[idx] = cn;
    g_histH[s * Bz * Hsz + idx] = hn;
    g_histC[s * Bz * Hsz + idx] = cn;
}

// ---------------- decoder init ----------------
__global__ void k_dec_init() {
    int idx = blockIdx.x * blockDim.x + threadIdx.x;
    if (idx >= NDEC * Hsz) return;
    int n = idx / Hsz, j = idx % Hsz;
    int b = n / (Sz - 1), s = n % (Sz - 1);
    g_decH0[idx] = g_histH[(s * Bz + b) * Hsz + j];
    g_decC[idx]  = g_histC[(s * Bz + b) * Hsz + j];
}

// ---------------- single-pass online-LSE NLL ----------------
__global__ void k_nll(const int* __restrict__ sql, int t) {
    __shared__ float shm[8], shs[8];
    int n = blockIdx.x;
    int b = n / (Sz - 1), s = n % (Sz - 1);
    int len = sql[b * Sz + s + 1];
    if (t >= len) return;
    const float* row = g_logits + (size_t)n * Vz;
    float m = -INFINITY, sm = 0.f;
    for (int j = threadIdx.x; j < Vz; j += blockDim.x) {
        float x = row[j];
        if (x > m) { sm = sm * expf(m - x) + 1.f; m = x; }
        else        sm += expf(x - m);
    }
#pragma unroll
    for (int o = 16; o > 0; o >>= 1) {
        float m2 = __shfl_down_sync(0xffffffff, m, o);
        float s2 = __shfl_down_sync(0xffffffff, sm, o);
        float M = fmaxf(m, m2);
        sm = sm * expf(m - M) + s2 * expf(m2 - M);
        m = M;
    }
    int lane = threadIdx.x & 31, w = threadIdx.x >> 5;
    if (lane == 0) { shm[w] = m; shs[w] = sm; }
    __syncthreads();
    if (threadIdx.x == 0) {
        m = shm[0]; sm = shs[0];
        for (int i = 1; i < 8; i++) {
            float M = fmaxf(m, shm[i]);
            sm = sm * expf(m - M) + shs[i] * expf(shm[i] - M);
            m = M;
        }
        float lse = m + logf(sm);
        int tgt = g_decTgt[t * NDEC + n];
        atomicAdd(&g_dloss, lse - row[tgt]);
        atomicAdd(&g_dcnt, 1.0f);
    }
}

__global__ void k_final(float* out) {
    float dec = (g_dcnt > 0.f) ? (g_dloss / g_dcnt) : 0.f;
    out[0] = g_click / (float)(Bz * Dz * Sz) + dec;
}

// ---------------- host helpers ----------------
static inline void tf32_store(const int* tok, const float* emb,
                              const float* W0, const float* W1, int ldw,
                              const float* b0, const float* b1,
                              float* C, int M, int N, int K,
                              int lanes, int half,
                              const int* cntF, const int* cntB)
{
    dim3 grid(N / 128, (M + 127) / 128);
    gemm_tf32<<<grid, 256>>>(nullptr, 0, tok, emb, W0, W1, ldw, b0, b1,
                             C, N, M, N, K, lanes, half, MODE_STORE,
                             cntF, cntB, nullptr, nullptr, nullptr, nullptr, 0, 0);
}
static inline void tf32_cell(const float* hIn, const float* W0, const float* W1, int ldw,
                             const float* xg, int M, int N, int K,
                             int lanes, int half, const int* cntF, const int* cntB,
                             float* hOut, float* cState, float* rmax,
                             const int* lens, int T, int t)
{
    dim3 grid(N / 128, (M + 127) / 128);
    gemm_tf32<<<grid, 256>>>(hIn, K, nullptr, nullptr, W0, W1, ldw, nullptr, nullptr,
                             (float*)xg, N, M, N, K, lanes, half, MODE_CELL,
                             cntF, cntB, hOut, cState, rmax, lens, T, t);
}
static inline void small_mode(const float* A, int lda, const float* W, int ldw,
                              const float* bias, float* C, int ldc,
                              int M, int N, int K, int mode)
{
    dim3 grid(N / 64, (M + 63) / 64);
    gemm_small<<<grid, 256>>>(A, lda, W, ldw, bias, C, ldc, M, N, K, mode);
}

#define GETSYM(var, sym) do { void* p_; cudaGetSymbolAddress(&p_, sym); var = (decltype(var))p_; } while (0)

extern "C" void kernel_launch(void* const* d_in, const int* in_sizes, int n_in,
                              void* d_out, int out_size)
{
    (void)in_sizes; (void)n_in; (void)out_size;
    const int*   sq     = (const int*)d_in[0];
    const int*   sql    = (const int*)d_in[1];
    const int*   rd     = (const int*)d_in[2];
    const int*   rdl    = (const int*)d_in[3];
    const float* labels = (const float*)d_in[4];
    const float* emb    = (const float*)d_in[5];
    const float* qWihf  = (const float*)d_in[6];
    const float* qWhhf  = (const float*)d_in[7];
    const float* qbf    = (const float*)d_in[8];
    const float* qWihb  = (const float*)d_in[9];
    const float* qWhhb  = (const float*)d_in[10];
    const float* qbb    = (const float*)d_in[11];
    const float* dWihf  = (const float*)d_in[12];
    const float* dWhhf  = (const float*)d_in[13];
    const float* dbf    = (const float*)d_in[14];
    const float* dWihb  = (const float*)d_in[15];
    const float* dWhhb  = (const float*)d_in[16];
    const float* dbb    = (const float*)d_in[17];
    const float* sWih   = (const float*)d_in[18];
    const float* sWhh   = (const float*)d_in[19];
    const float* sb     = (const float*)d_in[20];
    const float* projW  = (const float*)d_in[21];
    const float* projb  = (const float*)d_in[22];
    const float* decWih = (const float*)d_in[23];
    const float* decWhh = (const float*)d_in[24];
    const float* decb   = (const float*)d_in[25];
    const float* outW   = (const float*)d_in[26];
    const float* outb   = (const float*)d_in[27];

    float *qGates, *dGates, *decGates, *logits;
    float *qh[2], *qc, *qrmax, *dh[2], *dc, *drmax, *encq, *sessH;
    float *decH[2], *decC, *comb, *sgates;
    int *qTok, *dTok, *decTok, *cntF, *cntB, *slenD;
    GETSYM(qGates, g_qGates);     GETSYM(dGates, g_dGates);
    GETSYM(decGates, g_decGates); GETSYM(logits, g_logits);
    GETSYM(qh[0], g_qh0); GETSYM(qh[1], g_qh1);
    GETSYM(qc, g_qc); GETSYM(qrmax, g_qrmax);
    GETSYM(dh[0], g_dh0); GETSYM(dh[1], g_dh1);
    GETSYM(dc, g_dc); GETSYM(drmax, g_drmax);
    GETSYM(encq, g_encq); GETSYM(sessH, g_sessH);
    GETSYM(decH[0], g_decH0); GETSYM(decH[1], g_decH1); GETSYM(decC, g_decC);
    GETSYM(comb, g_comb); GETSYM(sgates, g_sgates);
    GETSYM(qTok, g_qTok); GETSYM(dTok, g_dTok); GETSYM(decTok, g_decTok);
    GETSYM(cntF, g_cntF); GETSYM(cntB, g_cntB); GETSYM(slenD, g_slenD);

    const int TPB = 256;
    k_init_all<<<(NDH + TPB - 1) / TPB, TPB>>>();
    k_sortD<<<1, 256>>>(rdl);
    k_qtok<<<(QLz * QLANES + TPB - 1) / TPB, TPB>>>(sq);
    k_dtok<<<(DLz * DLANES + TPB - 1) / TPB, TPB>>>(rd);
    k_dectok<<<(TDEC * NDEC + TPB - 1) / TPB, TPB>>>(sq);

    // ---- x-part gates (tf32 gather GEMMs, interleaved gate layout) ----
    tf32_store(qTok, emb, qWihf, qWihb, Ez, qbf, qbb,
               qGates, QLz * QLANES, 4 * Hqz, Ez, QLANES, NQ, nullptr, nullptr);
    tf32_store(dTok, emb, dWihf, dWihb, Ez, dbf, dbb,
               dGates, DLz * DLANES, 4 * Hdz, Ez, DLANES, NDOC, cntF, cntB);
    tf32_store(decTok, emb, decWih, decWih, Ez, decb, decb,
               decGates, TDEC * NDEC, 4 * Hsz, Ez, TDEC * NDEC, TDEC * NDEC,
               nullptr, nullptr);

    // ---- query BiLSTM: tf32 fused recurrence+cell ----
    for (int t = 0; t < QLz; t++) {
        const float* xg = qGates + (size_t)t * QLANES * 4 * Hqz;
        tf32_cell(qh[t & 1], qWhhf, qWhhb, Hqz, xg,
                  QLANES, 4 * Hqz, Hqz, QLANES, NQ, nullptr, nullptr,
                  qh[(t + 1) & 1], qc, qrmax, sql, QLz, t);
    }

    // ---- doc BiLSTM: tf32 fused recurrence+cell with active-count skip ----
    for (int t = 0; t < DLz; t++) {
        const float* xg = dGates + (size_t)t * DLANES * 4 * Hdz;
        tf32_cell(dh[t & 1], dWhhf, dWhhb, Hdz, xg,
                  DLANES, 4 * Hdz, Hdz, DLANES, NDOC, cntF + t, cntB + t,
                  dh[(t + 1) & 1], dc, drmax, slenD, DLz, t);
    }

    k_build_encq<<<(NQ * 2 * Hqz + TPB - 1) / TPB, TPB>>>();
    k_build_encd<<<(NDOC * 2 * Hdz + TPB - 1) / TPB, TPB>>>();

    // ---- session loop (fp32 small) ----
    for (int s = 0; s < Sz; s++) {
        small_mode(encq + s * (2 * Hqz), Sz * 2 * Hqz, projW, 2 * Hqz + Hsz, projb,
                   comb, Hsz, Bz, Hsz, 2 * Hqz, MODE_STORE);
        small_mode(sessH, Hsz, projW + 2 * Hqz, 2 * Hqz + Hsz, nullptr,
                   comb, Hsz, Bz, Hsz, Hsz, MODE_ACC);
        k_score_bce<<<Bz, 256>>>(labels, s);
        small_mode(encq + s * (2 * Hqz), Sz * 2 * Hqz, sWih, 2 * Hqz, sb,
                   sgates, 4 * Hsz, Bz, 4 * Hsz, 2 * Hqz, MODE_STORE);
        small_mode(sessH, Hsz, sWhh, Hsz, nullptr,
                   sgates, 4 * Hsz, Bz, 4 * Hsz, Hsz, MODE_ACC);
        k_sess_cell<<<(Bz * Hsz + TPB - 1) / TPB, TPB>>>(s);
    }

    // ---- decoder: tf32 fused cell + tf32 logits + online NLL ----
    k_dec_init<<<(NDEC * Hsz + TPB - 1) / TPB, TPB>>>();
    for (int t = 0; t < TDEC; t++) {
        const float* xg = decGates + (size_t)t * NDEC * 4 * Hsz;
        tf32_cell(decH[t & 1], decWhh, decWhh, Hsz, xg,
                  NDEC, 4 * Hsz, Hsz, NDEC, NDEC, nullptr, nullptr,
                  decH[(t + 1) & 1], decC, nullptr, nullptr, 0, 0);
        k_logits_tf32<<<Vz / 256, 256>>>(decH[(t + 1) & 1], outW, outb, logits);
        k_nll<<<NDEC, 256>>>(sql, t);
    }

    k_final<<<1, 1>>>((float*)d_out);
}

// round 8
// speedup vs baseline: 1.2430x; 1.2315x over previous
#include <cuda_runtime.h>
#include <math.h>
#include <stdint.h>

// ---------------- problem constants ----------------
#define Bz   32
#define Sz   4
#define QLz  12
#define Dz   10
#define DLz  40
#define Vz   32000
#define Ez   256
#define Hqz  256
#define Hdz  256
#define Hsz  512

#define NQ     128
#define NDOC   1280
#define QLANES 256
#define DLANES 2560
#define NDEC   96
#define TDEC   11
#define NEGF   (-1000000000.0f)

#define MODE_STORE 0
#define MODE_ACC   1

#define DECNB  125   // Vz/256

// ---------------- scratch ----------------
__device__ float g_qGates[QLz * QLANES * 4 * Hqz];          // interleaved
__device__ float g_dGates[DLz * DLANES * 4 * Hdz];          // interleaved
__device__ float g_decGates[TDEC * NDEC * 4 * Hsz];         // interleaved

__device__ float g_qh0[QLANES * Hqz], g_qh1[QLANES * Hqz];
__device__ float g_qc[QLANES * Hqz], g_qrmax[QLANES * Hqz];
__device__ float g_dh0[DLANES * Hdz], g_dh1[DLANES * Hdz];
__device__ float g_dc[DLANES * Hdz], g_drmax[DLANES * Hdz];
__device__ float g_encq[NQ * 2 * Hqz];
__device__ float g_encd[NDOC * 2 * Hdz];
__device__ float g_sessH[Bz * Hsz], g_sessC[Bz * Hsz];
__device__ float g_histH[Sz * Bz * Hsz], g_histC[Sz * Bz * Hsz];
__device__ float g_combPre[Bz * Sz * Hsz];       // [b*S+s][512]
__device__ float g_sgatesPre[Bz * Sz * 4 * Hsz]; // [b*S+s][2048]
__device__ float g_decH0[NDEC * Hsz], g_decH1[NDEC * Hsz], g_decC[NDEC * Hsz];

__device__ int g_qTok[QLz * QLANES];
__device__ int g_dTok[DLz * DLANES];
__device__ int g_decTok[TDEC * NDEC];
__device__ int g_decTgt[TDEC * NDEC];

__device__ int g_permD[NDOC];
__device__ int g_ilaneD[NDOC];
__device__ int g_slenD[NDOC];
__device__ int g_cntF[DLz];
__device__ int g_cntB[DLz];

// decoder NLL partials
__device__ float g_partM[DECNB * NDEC];
__device__ float g_partS[DECNB * NDEC];
__device__ float g_tgtLogit[NDEC];

__device__ float g_click, g_dloss, g_dcnt;

// grid-barrier state (reset every launch by k_init_all)
__device__ unsigned g_barCnt[4];
__device__ unsigned g_barGen[4];

__device__ __forceinline__ float sigf(float x) { return 1.0f / (1.0f + expf(-x)); }

__device__ __forceinline__ uint32_t f2tf(float f) {
    uint32_t u;
    asm("cvt.rna.tf32.f32 %0, %1;" : "=r"(u) : "f"(f));
    return u;
}
__device__ __forceinline__ void mma_tf32(float* d, uint32_t a0, uint32_t a1,
                                         uint32_t a2, uint32_t a3,
                                         uint32_t b0, uint32_t b1) {
    asm volatile(
        "mma.sync.aligned.m16n8k8.row.col.f32.tf32.tf32.f32 "
        "{%0,%1,%2,%3}, {%4,%5,%6,%7}, {%8,%9}, {%0,%1,%2,%3};\n"
        : "+f"(d[0]), "+f"(d[1]), "+f"(d[2]), "+f"(d[3])
        : "r"(a0), "r"(a1), "r"(a2), "r"(a3), "r"(b0), "r"(b1));
}

// weight row mapping for interleaved gate layout: out col c -> orig W row
__device__ __forceinline__ int wmap(int c, int Hn) {
    return (c & 3) * Hn + (c >> 2);
}

// software grid barrier; requires all nblocks co-resident
__device__ __forceinline__ void grid_barrier(int id, unsigned nblocks, unsigned expect) {
    __syncthreads();
    if (threadIdx.x == 0) {
        __threadfence();
        unsigned v = atomicAdd(&g_barCnt[id], 1u);
        if (v == nblocks - 1u) {
            atomicExch(&g_barCnt[id], 0u);
            __threadfence();
            atomicExch(&g_barGen[id], expect);
        } else {
            while (*((volatile unsigned*)&g_barGen[id]) < expect) { }
        }
        __threadfence();
    }
    __syncthreads();
}

// =======================================================================
// TF32 gather GEMM (MODE_STORE only): 128x128 tile, 8 warps
// C[M][N] = emb[tok[r]] . Wrow(wmap(n)) + bias   (interleaved gate layout)
// Dual weights at 128-row tile granularity; optional cntF/cntB skip.
// =======================================================================
__global__ __launch_bounds__(256) void gemm_tf32_store(
    const int* __restrict__ tok, const float* __restrict__ emb,
    const float* __restrict__ W0, const float* __restrict__ W1, int ldw,
    const float* __restrict__ b0, const float* __restrict__ b1,
    float* __restrict__ C, int ldc,
    int M, int N, int K,
    int lanes, int halfLanes,
    const int* __restrict__ cntF, const int* __restrict__ cntB)
{
    const int row0 = blockIdx.y * 128;
    const int col0 = blockIdx.x * 128;
    const int Hn = N >> 2;

    const int lane0 = row0 % lanes;
    if (cntF) {
        const int tt = row0 / lanes;
        if (lane0 < halfLanes) { if (lane0 >= cntF[tt]) return; }
        else                   { if (lane0 - halfLanes >= cntB[tt]) return; }
    }
    const int dir = (lane0 < halfLanes) ? 0 : 1;
    const float* W    = dir ? W1 : W0;
    const float* bias = dir ? b1 : b0;

    __shared__ float As[128][17];
    __shared__ float Ws[128][17];

    const int tid  = threadIdx.x;
    const int warp = tid >> 5, lane = tid & 31;
    const int g  = lane >> 2, cq = lane & 3;
    const int wm0 = (warp & 1) * 64;
    const int wn0 = (warp >> 1) * 32;
    const int lr = tid >> 1;
    const int lk = (tid & 1) << 3;

    const int ar = row0 + lr;
    const bool aok = (ar < M);
    const float* arow = emb + (size_t)tok[aok ? ar : 0] * K;
    const float* wrow = W + (size_t)wmap(col0 + lr, Hn) * ldw;

    float acc[4][4][4];
#pragma unroll
    for (int i = 0; i < 4; i++)
#pragma unroll
        for (int j = 0; j < 4; j++)
#pragma unroll
            for (int v = 0; v < 4; v++) acc[i][j][v] = 0.0f;

    for (int k0 = 0; k0 < K; k0 += 16) {
        float4 av0 = aok ? *(const float4*)(arow + k0 + lk)     : make_float4(0,0,0,0);
        float4 av1 = aok ? *(const float4*)(arow + k0 + lk + 4) : make_float4(0,0,0,0);
        float4 wv0 = *(const float4*)(wrow + k0 + lk);
        float4 wv1 = *(const float4*)(wrow + k0 + lk + 4);
        As[lr][lk+0]=__uint_as_float(f2tf(av0.x)); As[lr][lk+1]=__uint_as_float(f2tf(av0.y));
        As[lr][lk+2]=__uint_as_float(f2tf(av0.z)); As[lr][lk+3]=__uint_as_float(f2tf(av0.w));
        As[lr][lk+4]=__uint_as_float(f2tf(av1.x)); As[lr][lk+5]=__uint_as_float(f2tf(av1.y));
        As[lr][lk+6]=__uint_as_float(f2tf(av1.z)); As[lr][lk+7]=__uint_as_float(f2tf(av1.w));
        Ws[lr][lk+0]=__uint_as_float(f2tf(wv0.x)); Ws[lr][lk+1]=__uint_as_float(f2tf(wv0.y));
        Ws[lr][lk+2]=__uint_as_float(f2tf(wv0.z)); Ws[lr][lk+3]=__uint_as_float(f2tf(wv0.w));
        Ws[lr][lk+4]=__uint_as_float(f2tf(wv1.x)); Ws[lr][lk+5]=__uint_as_float(f2tf(wv1.y));
        Ws[lr][lk+6]=__uint_as_float(f2tf(wv1.z)); Ws[lr][lk+7]=__uint_as_float(f2tf(wv1.w));
        __syncthreads();
#pragma unroll
        for (int kk = 0; kk < 16; kk += 8) {
            uint32_t bf[4][2];
#pragma unroll
            for (int nt = 0; nt < 4; nt++) {
                bf[nt][0] = __float_as_uint(Ws[wn0 + nt*8 + g][kk + cq]);
                bf[nt][1] = __float_as_uint(Ws[wn0 + nt*8 + g][kk + cq + 4]);
            }
#pragma unroll
            for (int mt = 0; mt < 4; mt++) {
                uint32_t a0 = __float_as_uint(As[wm0 + mt*16 + g    ][kk + cq]);
                uint32_t a1 = __float_as_uint(As[wm0 + mt*16 + g + 8][kk + cq]);
                uint32_t a2 = __float_as_uint(As[wm0 + mt*16 + g    ][kk + cq + 4]);
                uint32_t a3 = __float_as_uint(As[wm0 + mt*16 + g + 8][kk + cq + 4]);
#pragma unroll
                for (int nt = 0; nt < 4; nt++)
                    mma_tf32(acc[mt][nt], a0, a1, a2, a3, bf[nt][0], bf[nt][1]);
            }
        }
        __syncthreads();
    }

#pragma unroll
    for (int mt = 0; mt < 4; mt++) {
#pragma unroll
        for (int nt = 0; nt < 4; nt++) {
            const int cc = col0 + wn0 + nt*8 + 2*cq;
            float bx = bias ? bias[wmap(cc, Hn)] : 0.f;
            float by = bias ? bias[wmap(cc + 1, Hn)] : 0.f;
            const int r0 = row0 + wm0 + mt*16 + g;
            if (r0 < M) {
                float2 v = make_float2(acc[mt][nt][0] + bx, acc[mt][nt][1] + by);
                *(float2*)(C + (size_t)r0 * ldc + cc) = v;
            }
            const int r1 = r0 + 8;
            if (r1 < M) {
                float2 v = make_float2(acc[mt][nt][2] + bx, acc[mt][nt][3] + by);
                *(float2*)(C + (size_t)r1 * ldc + cc) = v;
            }
        }
    }
}

// =======================================================================
// PERSISTENT LSTM: one launch runs all T steps with grid barriers.
// Each block owns a fixed (128-row, 128-col) tile of the recurrence GEMM
// gates[t] (+)= h[t] @ W^T  (interleaved), fused LSTM cell epilogue.
// lanes % 128 == 0 (no M guards). Inactive tiles skip work, join barrier.
// =======================================================================
__global__ __launch_bounds__(256, 2) void persist_lstm(
    int barId, int nblocks, int nx,
    const float* __restrict__ W0, const float* __restrict__ W1, int ldw,
    float* __restrict__ gates, int stepStride,
    float* __restrict__ h0, float* __restrict__ h1,
    float* __restrict__ cState, float* __restrict__ rmax,
    const int* __restrict__ lens,
    const int* __restrict__ cntF, const int* __restrict__ cntB,
    int lanes, int halfLanes, int H, int T)
{
    const int bid  = blockIdx.x;
    const int row0 = (bid / nx) * 128;
    const int col0 = (bid % nx) * 128;
    const int K = H, N = 4 * H, Hn = H;

    const float* W = (row0 < halfLanes) ? W0 : W1;

    __shared__ float As[128][17];
    __shared__ float Ws[128][17];

    const int tid  = threadIdx.x;
    const int warp = tid >> 5, lane = tid & 31;
    const int g  = lane >> 2, cq = lane & 3;
    const int wm0 = (warp & 1) * 64;
    const int wn0 = (warp >> 1) * 32;
    const int lr = tid >> 1;
    const int lk = (tid & 1) << 3;

    const float* wrow = W + (size_t)wmap(col0 + lr, Hn) * ldw;

    for (int t = 0; t < T; t++) {
        bool active = true;
        if (cntF) active = (row0 < halfLanes) ? (row0 < cntF[t])
                                              : (row0 - halfLanes < cntB[t]);
        if (active) {
            const float* hIn  = (t & 1) ? h1 : h0;
            float*       hOut = (t & 1) ? h0 : h1;
            float* C = gates + (size_t)t * stepStride;
            const float* arow = hIn + (size_t)(row0 + lr) * K;

            float acc[4][4][4];
#pragma unroll
            for (int i = 0; i < 4; i++)
#pragma unroll
                for (int j = 0; j < 4; j++)
#pragma unroll
                    for (int v = 0; v < 4; v++) acc[i][j][v] = 0.0f;

            for (int k0 = 0; k0 < K; k0 += 16) {
                float4 av0 = *(const float4*)(arow + k0 + lk);
                float4 av1 = *(const float4*)(arow + k0 + lk + 4);
                float4 wv0 = *(const float4*)(wrow + k0 + lk);
                float4 wv1 = *(const float4*)(wrow + k0 + lk + 4);
                As[lr][lk+0]=__uint_as_float(f2tf(av0.x)); As[lr][lk+1]=__uint_as_float(f2tf(av0.y));
                As[lr][lk+2]=__uint_as_float(f2tf(av0.z)); As[lr][lk+3]=__uint_as_float(f2tf(av0.w));
                As[lr][lk+4]=__uint_as_float(f2tf(av1.x)); As[lr][lk+5]=__uint_as_float(f2tf(av1.y));
                As[lr][lk+6]=__uint_as_float(f2tf(av1.z)); As[lr][lk+7]=__uint_as_float(f2tf(av1.w));
                Ws[lr][lk+0]=__uint_as_float(f2tf(wv0.x)); Ws[lr][lk+1]=__uint_as_float(f2tf(wv0.y));
                Ws[lr][lk+2]=__uint_as_float(f2tf(wv0.z)); Ws[lr][lk+3]=__uint_as_float(f2tf(wv0.w));
                Ws[lr][lk+4]=__uint_as_float(f2tf(wv1.x)); Ws[lr][lk+5]=__uint_as_float(f2tf(wv1.y));
                Ws[lr][lk+6]=__uint_as_float(f2tf(wv1.z)); Ws[lr][lk+7]=__uint_as_float(f2tf(wv1.w));
                __syncthreads();
#pragma unroll
                for (int kk = 0; kk < 16; kk += 8) {
                    uint32_t bf[4][2];
#pragma unroll
                    for (int nt = 0; nt < 4; nt++) {
                        bf[nt][0] = __float_as_uint(Ws[wn0 + nt*8 + g][kk + cq]);
                        bf[nt][1] = __float_as_uint(Ws[wn0 + nt*8 + g][kk + cq + 4]);
                    }
#pragma unroll
                    for (int mt = 0; mt < 4; mt++) {
                        uint32_t a0 = __float_as_uint(As[wm0 + mt*16 + g    ][kk + cq]);
                        uint32_t a1 = __float_as_uint(As[wm0 + mt*16 + g + 8][kk + cq]);
                        uint32_t a2 = __float_as_uint(As[wm0 + mt*16 + g    ][kk + cq + 4]);
                        uint32_t a3 = __float_as_uint(As[wm0 + mt*16 + g + 8][kk + cq + 4]);
#pragma unroll
                        for (int nt = 0; nt < 4; nt++)
                            mma_tf32(acc[mt][nt], a0, a1, a2, a3, bf[nt][0], bf[nt][1]);
                    }
                }
                __syncthreads();
            }

            // fused LSTM cell epilogue (layout proven in R7)
#pragma unroll
            for (int mt = 0; mt < 4; mt++) {
#pragma unroll
                for (int nt = 0; nt < 4; nt++) {
                    float p0 = __shfl_xor_sync(0xffffffff, acc[mt][nt][0], 1);
                    float p1 = __shfl_xor_sync(0xffffffff, acc[mt][nt][1], 1);
                    float p2 = __shfl_xor_sync(0xffffffff, acc[mt][nt][2], 1);
                    float p3 = __shfl_xor_sync(0xffffffff, acc[mt][nt][3], 1);
                    if ((cq & 1) == 0) {
                        const int cc = col0 + wn0 + nt*8 + 2*cq;
                        const int j  = cc >> 2;
#pragma unroll
                        for (int half = 0; half < 2; half++) {
                            const int r = row0 + wm0 + mt*16 + g + half*8;
                            int n = (r < halfLanes) ? r : r - halfLanes;
                            int len = lens[n];
                            bool valid = (r < halfLanes) ? (t < len) : (t >= T - len);
                            if (!valid) continue;
                            float gi, gf, gg, go;
                            if (half == 0) { gi = acc[mt][nt][0]; gf = acc[mt][nt][1]; gg = p0; go = p1; }
                            else           { gi = acc[mt][nt][2]; gf = acc[mt][nt][3]; gg = p2; go = p3; }
                            float4 xg = *(const float4*)(C + (size_t)r * N + cc);
                            gi += xg.x; gf += xg.y; gg += xg.z; go += xg.w;
                            float cp = cState[(size_t)r * Hn + j];
                            float cn = sigf(gf) * cp + sigf(gi) * tanhf(gg);
                            float hn = sigf(go) * tanhf(cn);
                            cState[(size_t)r * Hn + j] = cn;
                            hOut[(size_t)r * Hn + j] = hn;
                            float rm = rmax[(size_t)r * Hn + j];
                            rmax[(size_t)r * Hn + j] = (hn > rm) ? hn : rm;
                        }
                    }
                }
            }
        }
        grid_barrier(barId, (unsigned)nblocks, (unsigned)(t + 1));
    }
}

// =======================================================================
// PERSISTENT DECODER: 125 blocks; per step:
//  A) blocks 0..15: tf32 fused cell (M=96, N=2048, K=512)
//  B) all: tf32 logits fragments (256 cols/block) + per-block LSE partials
//     + target-logit extraction (logits never materialized)
//  C) block 0: combine partials, accumulate masked NLL in registers
// =======================================================================
__global__ __launch_bounds__(256) void persist_dec(
    const float* __restrict__ Whh,            // decWhh [2048][512]
    const float* __restrict__ gates,          // decGates [T][96][2048] interleaved
    const float* __restrict__ outW,           // [32000][512]
    const float* __restrict__ outb,
    const int* __restrict__ sql)
{
    __shared__ float SA[128][17];
    __shared__ float SW[256][17];
    __shared__ float sPM[NDEC][9];
    __shared__ float sPS[NDEC][9];

    const int bid = blockIdx.x;
    const int tid = threadIdx.x;
    const int warp = tid >> 5, lane = tid & 31;
    const int g = lane >> 2, cq = lane & 3;

    float lloss = 0.f, lcnt = 0.f;
    int myLen = 0;
    if (bid == 0 && tid < NDEC) {
        int b = tid / (Sz - 1), s = tid % (Sz - 1);
        myLen = sql[b * Sz + s + 1];
    }

    for (int t = 0; t < TDEC; t++) {
        const float* hIn  = (t & 1) ? g_decH1 : g_decH0;
        float*       hOut = (t & 1) ? g_decH0 : g_decH1;

        // ---------- phase A: cell ----------
        if (bid < 16) {
            const int col0 = bid * 128;
            const int wm0 = (warp & 1) * 64;
            const int wn0 = (warp >> 1) * 32;
            const int lr = tid >> 1;
            const int lk = (tid & 1) << 3;
            const bool aok = (lr < NDEC);
            const float* arow = hIn + (size_t)(aok ? lr : 0) * Hsz;
            const float* wrow = Whh + (size_t)wmap(col0 + lr, Hsz) * Hsz;
            const float* C = gates + (size_t)t * NDEC * 4 * Hsz;

            float acc[4][4][4];
#pragma unroll
            for (int i = 0; i < 4; i++)
#pragma unroll
                for (int j = 0; j < 4; j++)
#pragma unroll
                    for (int v = 0; v < 4; v++) acc[i][j][v] = 0.0f;

            for (int k0 = 0; k0 < Hsz; k0 += 16) {
                float4 av0 = aok ? *(const float4*)(arow + k0 + lk)     : make_float4(0,0,0,0);
                float4 av1 = aok ? *(const float4*)(arow + k0 + lk + 4) : make_float4(0,0,0,0);
                float4 wv0 = *(const float4*)(wrow + k0 + lk);
                float4 wv1 = *(const float4*)(wrow + k0 + lk + 4);
                SA[lr][lk+0]=__uint_as_float(f2tf(av0.x)); SA[lr][lk+1]=__uint_as_float(f2tf(av0.y));
                SA[lr][lk+2]=__uint_as_float(f2tf(av0.z)); SA[lr][lk+3]=__uint_as_float(f2tf(av0.w));
                SA[lr][lk+4]=__uint_as_float(f2tf(av1.x)); SA[lr][lk+5]=__uint_as_float(f2tf(av1.y));
                SA[lr][lk+6]=__uint_as_float(f2tf(av1.z)); SA[lr][lk+7]=__uint_as_float(f2tf(av1.w));
                SW[lr][lk+0]=__uint_as_float(f2tf(wv0.x)); SW[lr][lk+1]=__uint_as_float(f2tf(wv0.y));
                SW[lr][lk+2]=__uint_as_float(f2tf(wv0.z)); SW[lr][lk+3]=__uint_as_float(f2tf(wv0.w));
                SW[lr][lk+4]=__uint_as_float(f2tf(wv1.x)); SW[lr][lk+5]=__uint_as_float(f2tf(wv1.y));
                SW[lr][lk+6]=__uint_as_float(f2tf(wv1.z)); SW[lr][lk+7]=__uint_as_float(f2tf(wv1.w));
                __syncthreads();
#pragma unroll
                for (int kk = 0; kk < 16; kk += 8) {
                    uint32_t bf[4][2];
#pragma unroll
                    for (int nt = 0; nt < 4; nt++) {
                        bf[nt][0] = __float_as_uint(SW[wn0 + nt*8 + g][kk + cq]);
                        bf[nt][1] = __float_as_uint(SW[wn0 + nt*8 + g][kk + cq + 4]);
                    }
#pragma unroll
                    for (int mt = 0; mt < 4; mt++) {
                        uint32_t a0 = __float_as_uint(SA[wm0 + mt*16 + g    ][kk + cq]);
                        uint32_t a1 = __float_as_uint(SA[wm0 + mt*16 + g + 8][kk + cq]);
                        uint32_t a2 = __float_as_uint(SA[wm0 + mt*16 + g    ][kk + cq + 4]);
                        uint32_t a3 = __float_as_uint(SA[wm0 + mt*16 + g + 8][kk + cq + 4]);
#pragma unroll
                        for (int nt = 0; nt < 4; nt++)
                            mma_tf32(acc[mt][nt], a0, a1, a2, a3, bf[nt][0], bf[nt][1]);
                    }
                }
                __syncthreads();
            }

#pragma unroll
            for (int mt = 0; mt < 4; mt++) {
#pragma unroll
                for (int nt = 0; nt < 4; nt++) {
                    float p0 = __shfl_xor_sync(0xffffffff, acc[mt][nt][0], 1);
                    float p1 = __shfl_xor_sync(0xffffffff, acc[mt][nt][1], 1);
                    float p2 = __shfl_xor_sync(0xffffffff, acc[mt][nt][2], 1);
                    float p3 = __shfl_xor_sync(0xffffffff, acc[mt][nt][3], 1);
                    if ((cq & 1) == 0) {
                        const int cc = col0 + wn0 + nt*8 + 2*cq;
                        const int j  = cc >> 2;
#pragma unroll
                        for (int half = 0; half < 2; half++) {
                            const int r = wm0 + mt*16 + g + half*8;
                            if (r >= NDEC) continue;
                            float gi, gf, gg, go;
                            if (half == 0) { gi = acc[mt][nt][0]; gf = acc[mt][nt][1]; gg = p0; go = p1; }
                            else           { gi = acc[mt][nt][2]; gf = acc[mt][nt][3]; gg = p2; go = p3; }
                            float4 xg = *(const float4*)(C + (size_t)r * (4*Hsz) + cc);
                            gi += xg.x; gf += xg.y; gg += xg.z; go += xg.w;
                            float cp = g_decC[(size_t)r * Hsz + j];
                            float cn = sigf(gf) * cp + sigf(gi) * tanhf(gg);
                            float hn = sigf(go) * tanhf(cn);
                            g_decC[(size_t)r * Hsz + j] = cn;
                            hOut[(size_t)r * Hsz + j] = hn;
                        }
                    }
                }
            }
        }
        grid_barrier(3, DECNB, (unsigned)(3*t + 1));

        // ---------- phase B: logits + LSE partials ----------
        {
            const float* h = hOut;   // h_{t+1}
            const int ncol0 = bid * 256;
            const int wn0 = warp * 32;

            float acc[6][4][4];
#pragma unroll
            for (int m = 0; m < 6; m++)
#pragma unroll
                for (int n = 0; n < 4; n++)
#pragma unroll
                    for (int v = 0; v < 4; v++) acc[m][n][v] = 0.0f;

            for (int k0 = 0; k0 < Hsz; k0 += 16) {
                // load A: 96 rows x 16 k (384 float4s)
                for (int i = tid; i < NDEC * 4; i += 256) {
                    int row = i >> 2, q = (i & 3) << 2;
                    float4 v = *(const float4*)(h + (size_t)row * Hsz + k0 + q);
                    SA[row][q+0]=__uint_as_float(f2tf(v.x)); SA[row][q+1]=__uint_as_float(f2tf(v.y));
                    SA[row][q+2]=__uint_as_float(f2tf(v.z)); SA[row][q+3]=__uint_as_float(f2tf(v.w));
                }
                // load W: 256 rows x 16 k (1024 float4s)
                for (int i = tid; i < 256 * 4; i += 256) {
                    int row = i >> 2, q = (i & 3) << 2;
                    float4 v = *(const float4*)(outW + (size_t)(ncol0 + row) * Hsz + k0 + q);
                    SW[row][q+0]=__uint_as_float(f2tf(v.x)); SW[row][q+1]=__uint_as_float(f2tf(v.y));
                    SW[row][q+2]=__uint_as_float(f2tf(v.z)); SW[row][q+3]=__uint_as_float(f2tf(v.w));
                }
                __syncthreads();
#pragma unroll
                for (int kk = 0; kk < 16; kk += 8) {
                    uint32_t bf[4][2];
#pragma unroll
                    for (int nt = 0; nt < 4; nt++) {
                        bf[nt][0] = __float_as_uint(SW[wn0 + nt*8 + g][kk + cq]);
                        bf[nt][1] = __float_as_uint(SW[wn0 + nt*8 + g][kk + cq + 4]);
                    }
#pragma unroll
                    for (int mt = 0; mt < 6; mt++) {
                        uint32_t a0 = __float_as_uint(SA[mt*16 + g    ][kk + cq]);
                        uint32_t a1 = __float_as_uint(SA[mt*16 + g + 8][kk + cq]);
                        uint32_t a2 = __float_as_uint(SA[mt*16 + g    ][kk + cq + 4]);
                        uint32_t a3 = __float_as_uint(SA[mt*16 + g + 8][kk + cq + 4]);
#pragma unroll
                        for (int nt = 0; nt < 4; nt++)
                            mma_tf32(acc[mt][nt], a0, a1, a2, a3, bf[nt][0], bf[nt][1]);
                    }
                }
                __syncthreads();
            }

            // bias; per-row LSE partial over this block's 256 cols; tgt extraction
            float bb[4][2];
#pragma unroll
            for (int nt = 0; nt < 4; nt++) {
                bb[nt][0] = outb[ncol0 + wn0 + nt*8 + 2*cq];
                bb[nt][1] = outb[ncol0 + wn0 + nt*8 + 2*cq + 1];
            }
#pragma unroll
            for (int mt = 0; mt < 6; mt++) {
#pragma unroll
                for (int half = 0; half < 2; half++) {
                    const int row = mt*16 + g + half*8;
                    float vv[8];
                    float mx = -1e30f;
#pragma unroll
                    for (int nt = 0; nt < 4; nt++) {
#pragma unroll
                        for (int j = 0; j < 2; j++) {
                            float v = acc[mt][nt][half*2 + j] + bb[nt][j];
                            vv[nt*2 + j] = v;
                            mx = fmaxf(mx, v);
                        }
                    }
                    // target extraction (unique owner writes)
                    int tg = g_decTgt[t * NDEC + row];
#pragma unroll
                    for (int nt = 0; nt < 4; nt++) {
#pragma unroll
                        for (int j = 0; j < 2; j++) {
                            int col = ncol0 + wn0 + nt*8 + 2*cq + j;
                            if (col == tg) g_tgtLogit[row] = vv[nt*2 + j];
                        }
                    }
                    // quad reduce (lanes g*4+cq share row)
                    float m1 = fmaxf(mx, __shfl_xor_sync(0xffffffff, mx, 1));
                    float m2 = fmaxf(m1, __shfl_xor_sync(0xffffffff, m1, 2));
                    float sm = 0.f;
#pragma unroll
                    for (int k = 0; k < 8; k++) sm += expf(vv[k] - m2);
                    sm += __shfl_xor_sync(0xffffffff, sm, 1);
                    sm += __shfl_xor_sync(0xffffffff, sm, 2);
                    if (cq == 0) { sPM[row][warp] = m2; sPS[row][warp] = sm; }
                }
            }
            __syncthreads();
            if (tid < NDEC) {
                float m = -1e30f;
#pragma unroll
                for (int w = 0; w < 8; w++) m = fmaxf(m, sPM[tid][w]);
                float s = 0.f;
#pragma unroll
                for (int w = 0; w < 8; w++) s += sPS[tid][w] * expf(sPM[tid][w] - m);
                g_partM[bid * NDEC + tid] = m;
                g_partS[bid * NDEC + tid] = s;
            }
            __syncthreads();
        }
        grid_barrier(3, DECNB, (unsigned)(3*t + 2));

        // ---------- phase C: combine ----------
        if (bid == 0 && tid < NDEC) {
            float m = -1e30f, s = 0.f;
            for (int p = 0; p < DECNB; p++) {
                float pm = g_partM[p * NDEC + tid];
                float ps = g_partS[p * NDEC + tid];
                float M = fmaxf(m, pm);
                s = s * expf(m - M) + ps * expf(pm - M);
                m = M;
            }
            float lse = m + logf(s);
            if (t < myLen) { lloss += lse - g_tgtLogit[tid]; lcnt += 1.f; }
        }
        grid_barrier(3, DECNB, (unsigned)(3*t + 3));
    }

    if (bid == 0) {
        if (tid < NDEC) { sPM[tid][0] = lloss; sPS[tid][0] = lcnt; }
        __syncthreads();
        if (tid == 0) {
            float L = 0.f, C = 0.f;
            for (int i = 0; i < NDEC; i++) { L += sPM[i][0]; C += sPS[i][0]; }
            g_dloss = L; g_dcnt = C;
        }
    }
}

// =======================================================================
// SMALL fp32 GEMM: 64x64 tile (session path)
// =======================================================================
__global__ __launch_bounds__(256) void gemm_small(
    const float* __restrict__ A, int lda,
    const float* __restrict__ W, int ldw,
    const float* __restrict__ bias,
    float* __restrict__ C, int ldc,
    int M, int N, int K, int mode)
{
    __shared__ float As[16][65];
    __shared__ float Ws[16][65];

    const int tid  = threadIdx.x;
    const int row0 = blockIdx.y * 64;
    const int col0 = blockIdx.x * 64;

    const int lr = tid >> 2;
    const int lk = (tid & 3) << 2;
    const int ty4 = (tid >> 4) << 2;
    const int tx4 = (tid & 15) << 2;

    float acc[4][4];
#pragma unroll
    for (int i = 0; i < 4; i++)
#pragma unroll
        for (int j = 0; j < 4; j++) acc[i][j] = 0.0f;

    const int ar = row0 + lr;
    const float* arow = A + (size_t)((ar < M) ? ar : 0) * lda;
    const float* wrow = W + (size_t)(col0 + lr) * ldw;
    const bool arow_ok = (ar < M);

    for (int k0 = 0; k0 < K; k0 += 16) {
        float4 av = *(const float4*)(arow + k0 + lk);
        if (!arow_ok) av = make_float4(0.f, 0.f, 0.f, 0.f);
        float4 wv = *(const float4*)(wrow + k0 + lk);
        As[lk + 0][lr] = av.x; As[lk + 1][lr] = av.y;
        As[lk + 2][lr] = av.z; As[lk + 3][lr] = av.w;
        Ws[lk + 0][lr] = wv.x; Ws[lk + 1][lr] = wv.y;
        Ws[lk + 2][lr] = wv.z; Ws[lk + 3][lr] = wv.w;
        __syncthreads();
#pragma unroll
        for (int k = 0; k < 16; k++) {
            float a0 = As[k][ty4 + 0], a1 = As[k][ty4 + 1];
            float a2 = As[k][ty4 + 2], a3 = As[k][ty4 + 3];
            float w0 = Ws[k][tx4 + 0], w1 = Ws[k][tx4 + 1];
            float w2 = Ws[k][tx4 + 2], w3 = Ws[k][tx4 + 3];
            acc[0][0] += a0 * w0; acc[0][1] += a0 * w1; acc[0][2] += a0 * w2; acc[0][3] += a0 * w3;
            acc[1][0] += a1 * w0; acc[1][1] += a1 * w1; acc[1][2] += a1 * w2; acc[1][3] += a1 * w3;
            acc[2][0] += a2 * w0; acc[2][1] += a2 * w1; acc[2][2] += a2 * w2; acc[2][3] += a2 * w3;
            acc[3][0] += a3 * w0; acc[3][1] += a3 * w1; acc[3][2] += a3 * w2; acc[3][3] += a3 * w3;
        }
        __syncthreads();
    }

#pragma unroll
    for (int i = 0; i < 4; i++) {
        int r = row0 + ty4 + i;
        if (r >= M) continue;
        float* cp = C + (size_t)r * ldc + col0 + tx4;
#pragma unroll
        for (int jj = 0; jj < 4; jj++) {
            float v = acc[i][jj];
            if (mode == MODE_ACC) v += cp[jj];
            else if (bias) v += bias[col0 + tx4 + jj];
            cp[jj] = v;
        }
    }
}

// ---------------- merged init ----------------
#define NQH (QLANES * Hqz)
#define NDH (DLANES * Hdz)
__global__ void k_init_all() {
    int i = blockIdx.x * blockDim.x + threadIdx.x;
    if (i < NQH) { g_qh0[i] = 0.f; g_qh1[i] = 0.f; g_qc[i] = 0.f; g_qrmax[i] = NEGF; }
    if (i < NDH) { g_dh0[i] = 0.f; g_dh1[i] = 0.f; g_dc[i] = 0.f; g_drmax[i] = NEGF; }
    if (i < Bz * Hsz) { g_sessH[i] = 0.f; g_sessC[i] = 0.f; }
    if (i == 0) {
        g_click = 0.f; g_dloss = 0.f; g_dcnt = 0.f;
        for (int k = 0; k < 4; k++) { g_barCnt[k] = 0u; g_barGen[k] = 0u; }
    }
}

// ---------------- doc counting sort ----------------
__global__ void k_sortD(const int* __restrict__ rdl) {
    __shared__ int hist[DLz + 1];
    __shared__ int off[DLz + 1];
    int tid = threadIdx.x;
    for (int i = tid; i <= DLz; i += blockDim.x) hist[i] = 0;
    __syncthreads();
    for (int i = tid; i < NDOC; i += blockDim.x) atomicAdd(&hist[rdl[i]], 1);
    __syncthreads();
    if (tid == 0) {
        int acc = 0;
        for (int l = DLz; l >= 1; l--) { off[l] = acc; acc += hist[l]; }
    }
    __syncthreads();
    for (int t = tid; t < DLz; t += blockDim.x) {
        int cf = 0, cb = 0;
        for (int l = t + 1; l <= DLz; l++) cf += hist[l];
        for (int l = DLz - t; l <= DLz; l++) cb += hist[l];
        g_cntF[t] = cf;
        g_cntB[t] = cb;
    }
    __syncthreads();
    for (int i = tid; i < NDOC; i += blockDim.x) {
        int len = rdl[i];
        int pos = atomicAdd(&off[len], 1);
        g_permD[pos] = i;
        g_slenD[pos] = len;
        g_ilaneD[i] = pos;
    }
}

// ---------------- token tables ----------------
__global__ void k_qtok(const int* __restrict__ sq) {
    int i = blockIdx.x * blockDim.x + threadIdx.x;
    if (i >= QLz * QLANES) return;
    int t = i / QLANES, lane = i % QLANES;
    int n  = (lane < NQ) ? lane : lane - NQ;
    int tt = (lane < NQ) ? t : (QLz - 1 - t);
    g_qTok[i] = sq[n * QLz + tt];
}
__global__ void k_dtok(const int* __restrict__ rd) {
    int i = blockIdx.x * blockDim.x + threadIdx.x;
    if (i >= DLz * DLANES) return;
    int t = i / DLANES, lane = i % DLANES;
    int slane = (lane < NDOC) ? lane : lane - NDOC;
    int doc = g_permD[slane];
    int tt = (lane < NDOC) ? t : (DLz - 1 - t);
    g_dTok[i] = rd[doc * DLz + tt];
}
__global__ void k_dectok(const int* __restrict__ sq) {
    int i = blockIdx.x * blockDim.x + threadIdx.x;
    if (i >= TDEC * NDEC) return;
    int t = i / NDEC, n = i % NDEC;
    int b = n / (Sz - 1), s = n % (Sz - 1);
    const int* qrow = sq + (b * Sz + s + 1) * QLz;
    g_decTok[i] = qrow[t];
    g_decTgt[i] = qrow[t + 1];
}

// ---------------- encoder output assembly ----------------
__global__ void k_build_encq() {
    int i = blockIdx.x * blockDim.x + threadIdx.x;
    if (i >= NQ * 2 * Hqz) return;
    int n = i / (2 * Hqz), j = i % (2 * Hqz);
    g_encq[i] = (j < Hqz) ? g_qrmax[n * Hqz + j]
                          : g_qrmax[(NQ + n) * Hqz + (j - Hqz)];
}
__global__ void k_build_encd() {
    int i = blockIdx.x * blockDim.x + threadIdx.x;
    if (i >= NDOC * 2 * Hdz) return;
    int n = i / (2 * Hdz), j = i % (2 * Hdz);
    int lane = g_ilaneD[n];
    g_encd[i] = (j < Hdz) ? g_drmax[lane * Hdz + j]
                          : g_drmax[(NDOC + lane) * Hdz + (j - Hdz)];
}

// ---------------- reductions ----------------
__device__ __forceinline__ float blockReduceSum256(float v, float* sh) {
#pragma unroll
    for (int o = 16; o > 0; o >>= 1) v += __shfl_down_sync(0xffffffff, v, o);
    int lane = threadIdx.x & 31, w = threadIdx.x >> 5;
    if (lane == 0) sh[w] = v;
    __syncthreads();
    v = (threadIdx.x < 8) ? sh[threadIdx.x] : 0.f;
    if (w == 0) {
#pragma unroll
        for (int o = 4; o > 0; o >>= 1) v += __shfl_down_sync(0xffffffff, v, o);
    }
    __syncthreads();
    return v;
}

// ---------------- session score+BCE ----------------
__global__ void k_score_bce(const float* __restrict__ labels, int s) {
    __shared__ float comb[Hsz];
    __shared__ float red[8];
    int b = blockIdx.x;
    for (int j = threadIdx.x; j < Hsz; j += blockDim.x)
        comb[j] = tanhf(g_combPre[(b * Sz + s) * Hsz + j]);
    __syncthreads();
    float local = 0.f;
    for (int d = 0; d < Dz; d++) {
        const float* ed = g_encd + (size_t)(((b * Sz + s) * Dz + d)) * (2 * Hdz);
        float p = 0.f;
        for (int j = threadIdx.x; j < 2 * Hdz; j += blockDim.x)
            p += comb[j] * ed[j];
        float score = blockReduceSum256(p, red);
        if (threadIdx.x == 0) {
            float lab = labels[(b * Sz + s) * Dz + d];
            local += fmaxf(score, 0.f) - score * lab + log1pf(expf(-fabsf(score)));
        }
    }
    if (threadIdx.x == 0) atomicAdd(&g_click, local);
}

// ---------------- session cell ----------------
__global__ void k_sess_cell(int s) {
    int idx = blockIdx.x * blockDim.x + threadIdx.x;
    if (idx >= Bz * Hsz) return;
    int b = idx / Hsz, j = idx % Hsz;
    const float* g = g_sgatesPre + (size_t)(b * Sz + s) * 4 * Hsz;
    float gi = g[j], gf = g[Hsz + j], gg = g[2 * Hsz + j], go = g[3 * Hsz + j];
    float cn = sigf(gf) * g_sessC[idx] + sigf(gi) * tanhf(gg);
    float hn = sigf(go) * tanhf(cn);
    g_sessH[idx] = hn; g_sessC[idx] = cn;
    g_histH[s * Bz * Hsz + idx] = hn;
    g_histC[s * Bz * Hsz + idx] = cn;
}

// ---------------- decoder init ----------------
__global__ void k_dec_init() {
    int idx = blockIdx.x * blockDim.x + threadIdx.x;
    if (idx >= NDEC * Hsz) return;
    int n = idx / Hsz, j = idx % Hsz;
    int b = n / (Sz - 1), s = n % (Sz - 1);
    g_decH0[idx] = g_histH[(s * Bz + b) * Hsz + j];
    g_decC[idx]  = g_histC[(s * Bz + b) * Hsz + j];
}

__global__ void k_final(float* out) {
    float dec = (g_dcnt > 0.f) ? (g_dloss / g_dcnt) : 0.f;
    out[0] = g_click / (float)(Bz * Dz * Sz) + dec;
}

// ---------------- host helpers ----------------
static inline void tf32_store(const int* tok, const float* emb,
                              const float* W0, const float* W1, int ldw,
                              const float* b0, const float* b1,
                              float* C, int M, int N, int K,
                              int lanes, int half,
                              const int* cntF, const int* cntB)
{
    dim3 grid(N / 128, (M + 127) / 128);
    gemm_tf32_store<<<grid, 256>>>(tok, emb, W0, W1, ldw, b0, b1,
                                   C, N, M, N, K, lanes, half, cntF, cntB);
}
static inline void small_mode(const float* A, int lda, const float* W, int ldw,
                              const float* bias, float* C, int ldc,
                              int M, int N, int K, int mode)
{
    dim3 grid(N / 64, (M + 63) / 64);
    gemm_small<<<grid, 256>>>(A, lda, W, ldw, bias, C, ldc, M, N, K, mode);
}

#define GETSYM(var, sym) do { void* p_; cudaGetSymbolAddress(&p_, sym); var = (decltype(var))p_; } while (0)

extern "C" void kernel_launch(void* const* d_in, const int* in_sizes, int n_in,
                              void* d_out, int out_size)
{
    (void)in_sizes; (void)n_in; (void)out_size;
    const int*   sq     = (const int*)d_in[0];
    const int*   sql    = (const int*)d_in[1];
    const int*   rd     = (const int*)d_in[2];
    const int*   rdl    = (const int*)d_in[3];
    const float* labels = (const float*)d_in[4];
    const float* emb    = (const float*)d_in[5];
    const float* qWihf  = (const float*)d_in[6];
    const float* qWhhf  = (const float*)d_in[7];
    const float* qbf    = (const float*)d_in[8];
    const float* qWihb  = (const float*)d_in[9];
    const float* qWhhb  = (const float*)d_in[10];
    const float* qbb    = (const float*)d_in[11];
    const float* dWihf  = (const float*)d_in[12];
    const float* dWhhf  = (const float*)d_in[13];
    const float* dbf    = (const float*)d_in[14];
    const float* dWihb  = (const float*)d_in[15];
    const float* dWhhb  = (const float*)d_in[16];
    const float* dbb    = (const float*)d_in[17];
    const float* sWih   = (const float*)d_in[18];
    const float* sWhh   = (const float*)d_in[19];
    const float* sb     = (const float*)d_in[20];
    const float* projW  = (const float*)d_in[21];
    const float* projb  = (const float*)d_in[22];
    const float* decWih = (const float*)d_in[23];
    const float* decWhh = (const float*)d_in[24];
    const float* decb   = (const float*)d_in[25];
    const float* outW   = (const float*)d_in[26];
    const float* outb   = (const float*)d_in[27];

    float *qGates, *dGates, *decGates;
    float *qh0, *qh1, *qc, *qrmax, *dh0, *dh1, *dc, *drmax, *encq, *sessH;
    float *combPre, *sgatesPre;
    int *qTok, *dTok, *decTok, *cntF, *cntB, *slenD;
    GETSYM(qGates, g_qGates);     GETSYM(dGates, g_dGates);
    GETSYM(decGates, g_decGates);
    GETSYM(qh0, g_qh0); GETSYM(qh1, g_qh1);
    GETSYM(qc, g_qc); GETSYM(qrmax, g_qrmax);
    GETSYM(dh0, g_dh0); GETSYM(dh1, g_dh1);
    GETSYM(dc, g_dc); GETSYM(drmax, g_drmax);
    GETSYM(encq, g_encq); GETSYM(sessH, g_sessH);
    GETSYM(combPre, g_combPre); GETSYM(sgatesPre, g_sgatesPre);
    GETSYM(qTok, g_qTok); GETSYM(dTok, g_dTok); GETSYM(decTok, g_decTok);
    GETSYM(cntF, g_cntF); GETSYM(cntB, g_cntB); GETSYM(slenD, g_slenD);

    const int TPB = 256;
    k_init_all<<<(NDH + TPB - 1) / TPB, TPB>>>();
    k_sortD<<<1, 256>>>(rdl);
    k_qtok<<<(QLz * QLANES + TPB - 1) / TPB, TPB>>>(sq);
    k_dtok<<<(DLz * DLANES + TPB - 1) / TPB, TPB>>>(rd);
    k_dectok<<<(TDEC * NDEC + TPB - 1) / TPB, TPB>>>(sq);

    // ---- x-part gates (tf32 gather GEMMs, interleaved) ----
    tf32_store(qTok, emb, qWihf, qWihb, Ez, qbf, qbb,
               qGates, QLz * QLANES, 4 * Hqz, Ez, QLANES, NQ, nullptr, nullptr);
    tf32_store(dTok, emb, dWihf, dWihb, Ez, dbf, dbb,
               dGates, DLz * DLANES, 4 * Hdz, Ez, DLANES, NDOC, cntF, cntB);
    tf32_store(decTok, emb, decWih, decWih, Ez, decb, decb,
               decGates, TDEC * NDEC, 4 * Hsz, Ez, TDEC * NDEC, TDEC * NDEC,
               nullptr, nullptr);

    // ---- session x-parts, batched over all (b,s) ----
    small_mode(encq, 2 * Hqz, projW, 2 * Hqz + Hsz, projb,
               combPre, Hsz, Bz * Sz, Hsz, 2 * Hqz, MODE_STORE);
    small_mode(encq, 2 * Hqz, sWih, 2 * Hqz, sb,
               sgatesPre, 4 * Hsz, Bz * Sz, 4 * Hsz, 2 * Hqz, MODE_STORE);

    // ---- query BiLSTM: ONE persistent launch (16 blocks, 12 steps) ----
    persist_lstm<<<16, 256>>>(0, 16, 8, qWhhf, qWhhb, Hqz,
                              qGates, QLANES * 4 * Hqz,
                              qh0, qh1, qc, qrmax,
                              sql, nullptr, nullptr,
                              QLANES, NQ, Hqz, QLz);

    // ---- doc BiLSTM: ONE persistent launch (160 blocks, 40 steps) ----
    persist_lstm<<<160, 256>>>(1, 160, 8, dWhhf, dWhhb, Hdz,
                               dGates, DLANES * 4 * Hdz,
                               dh0, dh1, dc, drmax,
                               slenD, cntF, cntB,
                               DLANES, NDOC, Hdz, DLz);

    k_build_encq<<<(NQ * 2 * Hqz + TPB - 1) / TPB, TPB>>>();
    k_build_encd<<<(NDOC * 2 * Hdz + TPB - 1) / TPB, TPB>>>();

    // ---- session loop (h-dependent parts only) ----
    for (int s = 0; s < Sz; s++) {
        small_mode(sessH, Hsz, projW + 2 * Hqz, 2 * Hqz + Hsz, nullptr,
                   combPre + s * Hsz, Sz * Hsz, Bz, Hsz, Hsz, MODE_ACC);
        k_score_bce<<<Bz, 256>>>(labels, s);
        small_mode(sessH, Hsz, sWhh, Hsz, nullptr,
                   sgatesPre + s * 4 * Hsz, Sz * 4 * Hsz, Bz, 4 * Hsz, Hsz, MODE_ACC);
        k_sess_cell<<<(Bz * Hsz + TPB - 1) / TPB, TPB>>>(s);
    }

    // ---- decoder: ONE persistent launch (125 blocks, 11 steps) ----
    k_dec_init<<<(NDEC * Hsz + TPB - 1) / TPB, TPB>>>();
    persist_dec<<<DECNB, 256>>>(decWhh, decGates, outW, outb, sql);

    k_final<<<1, 1>>>((float*)d_out);
}